// round 5
// baseline (speedup 1.0000x reference)
#include <cuda_runtime.h>
#include <cuda_bf16.h>
#include <cstdint>

#define BWIN 4096
#define NTOK 49
#define DIM  256
#define NH   8
#define HD   32
#define MTOT (BWIN * NTOK)            /* 200704 */
#define QKV_S (BWIN * NH * NTOK * HD) /* 51380224 */

typedef unsigned long long u64;
typedef unsigned int u32;

// ---------------- device scratch (allocation-free) ----------------
__device__ float g_qkv[3ULL * QKV_S];                       // fp32 [3][B][H][N][hd]
__device__ float g_bias[NH * NTOK * NTOK];                  // [H][N][N]
__device__ __align__(16) __nv_bfloat16 g_xhi[(size_t)MTOT * DIM];
__device__ __align__(16) __nv_bfloat16 g_xlo[(size_t)MTOT * DIM];
__device__ __align__(16) __nv_bfloat16 g_ahi[(size_t)MTOT * DIM];
__device__ __align__(16) __nv_bfloat16 g_alo[(size_t)MTOT * DIM];
__device__ __align__(16) __nv_bfloat16 g_wqhi[768 * 256], g_wqlo[768 * 256];
__device__ __align__(16) __nv_bfloat16 g_wphi[256 * 256], g_wplo[256 * 256];

// ---------------- helpers ----------------
__device__ __forceinline__ u64 f2fma(u64 a, u64 b, u64 c) {
    u64 d;
    asm("fma.rn.f32x2 %0, %1, %2, %3;" : "=l"(d) : "l"(a), "l"(b), "l"(c));
    return d;
}
__device__ __forceinline__ u64 dup32(float x) {
    u64 d;
    asm("mov.b64 %0, {%1, %1};" : "=l"(d) : "r"(__float_as_uint(x)));
    return d;
}
__device__ __forceinline__ void split_bf(float x, unsigned short& h, unsigned short& l) {
    __nv_bfloat16 hb = __float2bfloat16(x);
    float r = x - __bfloat162float(hb);
    __nv_bfloat16 lb = __float2bfloat16(r);
    h = __bfloat16_as_ushort(hb);
    l = __bfloat16_as_ushort(lb);
}
__device__ __forceinline__ u32 smem_u32(const void* p) {
    u32 a;
    asm("{ .reg .u64 t; cvta.to.shared.u64 t, %1; cvt.u32.u64 %0, t; }" : "=r"(a) : "l"(p));
    return a;
}

__device__ __forceinline__ void mma16816(float* d, u32 a0, u32 a1, u32 a2, u32 a3,
                                         u32 b0, u32 b1) {
    asm volatile(
        "mma.sync.aligned.m16n8k16.row.col.f32.bf16.bf16.f32 "
        "{%0,%1,%2,%3}, {%4,%5,%6,%7}, {%8,%9}, {%0,%1,%2,%3};"
        : "+f"(d[0]), "+f"(d[1]), "+f"(d[2]), "+f"(d[3])
        : "r"(a0), "r"(a1), "r"(a2), "r"(a3), "r"(b0), "r"(b1));
}

#define LDSM_X4(r0, r1, r2, r3, addr) \
    asm volatile("ldmatrix.sync.aligned.m8n8.x4.shared.b16 {%0,%1,%2,%3}, [%4];" \
        : "=r"(r0), "=r"(r1), "=r"(r2), "=r"(r3) : "r"(addr))

#define CP_ASYNC16(s, g) \
    asm volatile("cp.async.cg.shared.global [%0], [%1], 16;" :: "r"(s), "l"(g))
#define CP_COMMIT() asm volatile("cp.async.commit_group;" ::: "memory")
#define CP_WAITG(n) asm volatile("cp.async.wait_group %0;" :: "n"(n) : "memory")

// ---------------- kernel: bias gather ----------------
__global__ void bias_kernel(const float* __restrict__ table, const int* __restrict__ rel) {
    int idx = blockIdx.x * 256 + threadIdx.x;
    if (idx < NH * NTOK * NTOK) {
        int h = idx / (NTOK * NTOK);
        int nm = idx - h * (NTOK * NTOK);
        g_bias[idx] = table[rel[nm] * NH + h];
    }
}

// ---------------- kernels: fp32 -> bf16 hi/lo ----------------
__global__ void conv_x(const float* __restrict__ x) {
    size_t i = (size_t)blockIdx.x * 256 + threadIdx.x;
    if (i < (size_t)MTOT * DIM / 4) {
        float4 v = ((const float4*)x)[i];
        unsigned short h0, h1, h2, h3, l0, l1, l2, l3;
        split_bf(v.x, h0, l0); split_bf(v.y, h1, l1);
        split_bf(v.z, h2, l2); split_bf(v.w, h3, l3);
        ((uint2*)g_xhi)[i] = make_uint2((u32)h0 | ((u32)h1 << 16), (u32)h2 | ((u32)h3 << 16));
        ((uint2*)g_xlo)[i] = make_uint2((u32)l0 | ((u32)l1 << 16), (u32)l2 | ((u32)l3 << 16));
    }
}
__global__ void conv_w(const float* __restrict__ w, int n4, int which) {
    int i = blockIdx.x * 256 + threadIdx.x;
    if (i < n4) {
        __nv_bfloat16* hi = which ? g_wphi : g_wqhi;
        __nv_bfloat16* lo = which ? g_wplo : g_wqlo;
        float4 v = ((const float4*)w)[i];
        unsigned short h0, h1, h2, h3, l0, l1, l2, l3;
        split_bf(v.x, h0, l0); split_bf(v.y, h1, l1);
        split_bf(v.z, h2, l2); split_bf(v.w, h3, l3);
        ((uint2*)hi)[i] = make_uint2((u32)h0 | ((u32)h1 << 16), (u32)h2 | ((u32)h3 << 16));
        ((uint2*)lo)[i] = make_uint2((u32)l0 | ((u32)l1 << 16), (u32)l2 | ((u32)l3 << 16));
    }
}

// ---------------- tensor-core GEMM (bf16 hi/lo, 4-stage cp.async pipeline) ----
#define KC      32
#define RSTRIDE 40                          /* elements; 80B rows, conflict-free */
#define TILE_E  (128 * RSTRIDE)
#define TILE_B  (TILE_E * 2)
#define STAGE_B (4 * TILE_B)                /* Ah, Al, Bh, Bl = 40960 B */
#define NSTAGE  4
#define SMEM_BYTES (NSTAGE * STAGE_B)       /* 163840 */

template <int MODE>
__global__ __launch_bounds__(256)
void gemm_mma(const float* __restrict__ bias, float* __restrict__ out) {
    extern __shared__ __nv_bfloat16 sm[];

    const __nv_bfloat16* Ah = MODE ? g_ahi : g_xhi;
    const __nv_bfloat16* Al = MODE ? g_alo : g_xlo;
    const __nv_bfloat16* Bh = MODE ? g_wphi : g_wqhi;
    const __nv_bfloat16* Bl = MODE ? g_wplo : g_wqlo;

    const int tid  = threadIdx.x;
    const int warp = tid >> 5;
    const int lane = tid & 31;
    const int g    = lane >> 2;
    const int t4   = lane & 3;
    const int wm   = warp >> 2;       // 0..1
    const int wn   = warp & 3;        // 0..3

    // N-block fastest (blockIdx.x) -> concurrent CTAs share A slice in L2
    const int    o0 = blockIdx.x * 128;
    const size_t m0 = (size_t)blockIdx.y * 128;

    const u32 smem_base = smem_u32(sm);

    // gmem -> smem copy mapping: 2 x 16B per tile per thread
    const int row0 = tid >> 2;
    const int row1 = row0 + 64;
    const int seg  = (tid & 3) * 8;

    const __nv_bfloat16* gA0h = Ah + (m0 + row0) * 256 + seg;
    const __nv_bfloat16* gA1h = Ah + (m0 + row1) * 256 + seg;
    const __nv_bfloat16* gA0l = Al + (m0 + row0) * 256 + seg;
    const __nv_bfloat16* gA1l = Al + (m0 + row1) * 256 + seg;
    const __nv_bfloat16* gB0h = Bh + (size_t)(o0 + row0) * 256 + seg;
    const __nv_bfloat16* gB1h = Bh + (size_t)(o0 + row1) * 256 + seg;
    const __nv_bfloat16* gB0l = Bl + (size_t)(o0 + row0) * 256 + seg;
    const __nv_bfloat16* gB1l = Bl + (size_t)(o0 + row1) * 256 + seg;

    const u32 s0b = (u32)(row0 * RSTRIDE + seg) * 2;
    const u32 s1b = (u32)(row1 * RSTRIDE + seg) * 2;

    // ldmatrix per-lane offsets (bytes, relative to stage base)
    const int q3 = (lane >> 3) & 1;
    const int q4 = (lane >> 4) & 1;
    const int r8 = lane & 7;
    const u32 offA  = 0 * TILE_B + (u32)(((wm * 64 + q3 * 8 + r8) * RSTRIDE) + q4 * 8) * 2;
    const u32 offB0 = 2 * TILE_B + (u32)(((wn * 32 + 0 * 16 + q4 * 8 + r8) * RSTRIDE) + q3 * 8) * 2;
    const u32 offB1 = 2 * TILE_B + (u32)(((wn * 32 + 1 * 16 + q4 * 8 + r8) * RSTRIDE) + q3 * 8) * 2;

    float acc[4][4][4];
#pragma unroll
    for (int a = 0; a < 4; ++a)
#pragma unroll
        for (int b = 0; b < 4; ++b)
#pragma unroll
            for (int c = 0; c < 4; ++c) acc[a][b][c] = 0.f;

#define ISSUE_STAGE(stg, kb) do {                                  \
        const u32 nx = smem_base + (u32)(stg) * STAGE_B;           \
        CP_ASYNC16(nx + 0 * TILE_B + s0b, gA0h + (kb));            \
        CP_ASYNC16(nx + 0 * TILE_B + s1b, gA1h + (kb));            \
        CP_ASYNC16(nx + 1 * TILE_B + s0b, gA0l + (kb));            \
        CP_ASYNC16(nx + 1 * TILE_B + s1b, gA1l + (kb));            \
        CP_ASYNC16(nx + 2 * TILE_B + s0b, gB0h + (kb));            \
        CP_ASYNC16(nx + 2 * TILE_B + s1b, gB1h + (kb));            \
        CP_ASYNC16(nx + 3 * TILE_B + s0b, gB0l + (kb));            \
        CP_ASYNC16(nx + 3 * TILE_B + s1b, gB1l + (kb));            \
        CP_COMMIT();                                               \
    } while (0)

    // ---- prologue: stages 0..2 ----
    ISSUE_STAGE(0, 0);
    ISSUE_STAGE(1, KC);
    ISSUE_STAGE(2, 2 * KC);

#pragma unroll 1
    for (int kc = 0; kc < 8; ++kc) {
        if (kc < 6)      CP_WAITG(2);
        else if (kc == 6) CP_WAITG(1);
        else              CP_WAITG(0);
        __syncthreads();

        if (kc + 3 <= 7) ISSUE_STAGE((kc + 3) & 3, (kc + 3) * KC);

        const u32 stb = smem_base + (u32)(kc & 3) * STAGE_B;
#pragma unroll
        for (int ks = 0; ks < 2; ++ks) {
            const u32 kso = (u32)(ks * 32);
            u32 bh[4][2], bl[4][2];
            LDSM_X4(bh[0][0], bh[0][1], bh[1][0], bh[1][1], stb + offB0 + kso);
            LDSM_X4(bh[2][0], bh[2][1], bh[3][0], bh[3][1], stb + offB1 + kso);
            LDSM_X4(bl[0][0], bl[0][1], bl[1][0], bl[1][1], stb + offB0 + TILE_B + kso);
            LDSM_X4(bl[2][0], bl[2][1], bl[3][0], bl[3][1], stb + offB1 + TILE_B + kso);
#pragma unroll
            for (int mi = 0; mi < 4; ++mi) {
                const u32 ao = stb + offA + (u32)(mi * 16 * RSTRIDE * 2) + kso;
                u32 ah0, ah1, ah2, ah3, al0, al1, al2, al3;
                LDSM_X4(ah0, ah1, ah2, ah3, ao);
                LDSM_X4(al0, al1, al2, al3, ao + TILE_B);
#pragma unroll
                for (int ni = 0; ni < 4; ++ni) {
                    mma16816(acc[mi][ni], ah0, ah1, ah2, ah3, bh[ni][0], bh[ni][1]);
                    mma16816(acc[mi][ni], al0, al1, al2, al3, bh[ni][0], bh[ni][1]);
                    mma16816(acc[mi][ni], ah0, ah1, ah2, ah3, bl[ni][0], bl[ni][1]);
                }
            }
        }
    }
#undef ISSUE_STAGE

    // ---- epilogue: bias add + store straight from registers ----
#pragma unroll
    for (int mi = 0; mi < 4; ++mi) {
        const int r0 = (int)m0 + wm * 64 + mi * 16 + g;
        const int r1 = r0 + 8;
#pragma unroll
        for (int ni = 0; ni < 4; ++ni) {
            const int c = o0 + wn * 32 + ni * 8 + 2 * t4;
            const float b0 = bias[c], b1 = bias[c + 1];
            float v00 = acc[mi][ni][0] + b0, v01 = acc[mi][ni][1] + b1;
            float v10 = acc[mi][ni][2] + b0, v11 = acc[mi][ni][3] + b1;
            if (MODE == 0) {
                const int which = c >> 8;
                const int head  = (c >> 5) & 7;
                const int d     = c & 31;
#pragma unroll
                for (int rr = 0; rr < 2; ++rr) {
                    const int m = rr ? r1 : r0;
                    const int bwin = m / NTOK;
                    const int n = m - bwin * NTOK;
                    float* dst = g_qkv + (size_t)which * QKV_S +
                        (((size_t)bwin * NH + head) * NTOK + n) * HD + d;
                    *(float2*)dst = rr ? make_float2(v10, v11) : make_float2(v00, v01);
                }
            } else {
                *(float2*)(out + (size_t)r0 * 256 + c) = make_float2(v00, v01);
                *(float2*)(out + (size_t)r1 * 256 + c) = make_float2(v10, v11);
            }
        }
    }
}

// ---------------- fused window attention (f32x2 register tiles) ----------------
__global__ __launch_bounds__(64)
void attn_kernel() {
    __shared__ __align__(16) float sq[NTOK][34], sk[NTOK][34], sv[NTOK][34];
    __shared__ float s[NTOK][50];

    const int tid = threadIdx.x;
    const int bh = blockIdx.x;
    const int bwin = bh >> 3;
    const int h = bh & 7;

    const size_t base = (size_t)bh * (NTOK * HD);
    const float4* q4 = (const float4*)(g_qkv + base);
    const float4* k4 = (const float4*)(g_qkv + (size_t)QKV_S + base);
    const float4* v4 = (const float4*)(g_qkv + 2ULL * QKV_S + base);

    for (int i = tid; i < NTOK * HD / 4; i += 64) {
        const int r = i >> 3, c = (i & 7) * 4;
        float4 a = q4[i];
        sq[r][c] = a.x; sq[r][c + 1] = a.y; sq[r][c + 2] = a.z; sq[r][c + 3] = a.w;
        float4 b = k4[i];
        sk[r][c] = b.x; sk[r][c + 1] = b.y; sk[r][c + 2] = b.z; sk[r][c + 3] = b.w;
        float4 d = v4[i];
        sv[r][c] = d.x; sv[r][c + 1] = d.y; sv[r][c + 2] = d.z; sv[r][c + 3] = d.w;
    }
    __syncthreads();

    if (tid < 49) {
        const int ti = tid / 7, tj = tid - ti * 7;
        const int n0 = ti * 7, m0 = tj * 7;
        u64 acc[7][7];
#pragma unroll
        for (int r = 0; r < 7; ++r)
#pragma unroll
            for (int cc = 0; cc < 7; ++cc) acc[r][cc] = 0ull;
#pragma unroll
        for (int kk = 0; kk < 16; ++kk) {
            u64 qv[7], kv[7];
#pragma unroll
            for (int r = 0; r < 7; ++r) qv[r] = *(const u64*)&sq[n0 + r][2 * kk];
#pragma unroll
            for (int cc = 0; cc < 7; ++cc) kv[cc] = *(const u64*)&sk[m0 + cc][2 * kk];
#pragma unroll
            for (int r = 0; r < 7; ++r)
#pragma unroll
                for (int cc = 0; cc < 7; ++cc) acc[r][cc] = f2fma(qv[r], kv[cc], acc[r][cc]);
        }
        const float scale = 0.17677669529663687f;
        const float* bb = g_bias + h * (NTOK * NTOK);
#pragma unroll
        for (int r = 0; r < 7; ++r)
#pragma unroll
            for (int cc = 0; cc < 7; ++cc) {
                const u64 a = acc[r][cc];
                const float lo = __uint_as_float((u32)(a & 0xffffffffull));
                const float hi = __uint_as_float((u32)(a >> 32));
                s[n0 + r][m0 + cc] = (lo + hi) * scale + bb[(n0 + r) * NTOK + m0 + cc];
            }
    }
    __syncthreads();

    if (tid < 49) {
        float mx = -1e30f;
#pragma unroll
        for (int c = 0; c < NTOK; ++c) mx = fmaxf(mx, s[tid][c]);
        float sum = 0.f;
#pragma unroll
        for (int c = 0; c < NTOK; ++c) {
            float e = __expf(s[tid][c] - mx);
            s[tid][c] = e;
            sum += e;
        }
        const float inv = 1.f / sum;
#pragma unroll
        for (int c = 0; c < NTOK; ++c) s[tid][c] *= inv;
    }
    __syncthreads();

    // P @ V: 56 threads (2 warps), 7(n) x 4(d) register tiles, f32x2 along d
    if (tid < 56) {
        const int ti = tid >> 3, tj = tid & 7;     // 7 n-groups x 8 d-groups
        const int n0 = ti * 7, d0 = tj * 4;
        u64 acc2[7][2];
#pragma unroll
        for (int r = 0; r < 7; ++r) { acc2[r][0] = 0ull; acc2[r][1] = 0ull; }
#pragma unroll 7
        for (int m = 0; m < NTOK; ++m) {
            const u64 v0 = *(const u64*)&sv[m][d0];
            const u64 v1 = *(const u64*)&sv[m][d0 + 2];
#pragma unroll
            for (int r = 0; r < 7; ++r) {
                const u64 sd = dup32(s[n0 + r][m]);
                acc2[r][0] = f2fma(sd, v0, acc2[r][0]);
                acc2[r][1] = f2fma(sd, v1, acc2[r][1]);
            }
        }
#pragma unroll
        for (int r = 0; r < 7; ++r) {
            unsigned short hh[4], ll[4];
#pragma unroll
            for (int cc = 0; cc < 2; ++cc) {
                const u64 a = acc2[r][cc];
                split_bf(__uint_as_float((u32)(a & 0xffffffffull)), hh[2 * cc], ll[2 * cc]);
                split_bf(__uint_as_float((u32)(a >> 32)), hh[2 * cc + 1], ll[2 * cc + 1]);
            }
            uint2 vh = make_uint2((u32)hh[0] | ((u32)hh[1] << 16), (u32)hh[2] | ((u32)hh[3] << 16));
            uint2 vl = make_uint2((u32)ll[0] | ((u32)ll[1] << 16), (u32)ll[2] | ((u32)ll[3] << 16));
            const size_t off = ((size_t)bwin * NTOK + n0 + r) * 256 + h * 32 + d0;
            *(uint2*)(g_ahi + off) = vh;
            *(uint2*)(g_alo + off) = vl;
        }
    }
}

// ---------------- launch ----------------
extern "C" void kernel_launch(void* const* d_in, const int* in_sizes, int n_in,
                              void* d_out, int out_size) {
    const float* x      = (const float*)d_in[0];
    const float* qkv_w  = (const float*)d_in[1];
    const float* qkv_b  = (const float*)d_in[2];
    const float* proj_w = (const float*)d_in[3];
    const float* proj_b = (const float*)d_in[4];
    const float* table  = (const float*)d_in[5];
    const int*   rel    = (const int*)d_in[6];
    float* out = (float*)d_out;

    static int smem_set = 0;
    if (!smem_set) {
        cudaFuncSetAttribute(gemm_mma<0>, cudaFuncAttributeMaxDynamicSharedMemorySize, SMEM_BYTES);
        cudaFuncSetAttribute(gemm_mma<1>, cudaFuncAttributeMaxDynamicSharedMemorySize, SMEM_BYTES);
        smem_set = 1;
    }

    bias_kernel<<<(NH * NTOK * NTOK + 255) / 256, 256>>>(table, rel);
    conv_x<<<(int)(((size_t)MTOT * DIM / 4 + 255) / 256), 256>>>(x);
    conv_w<<<(768 * 256 / 4 + 255) / 256, 256>>>(qkv_w, 768 * 256 / 4, 0);
    conv_w<<<(256 * 256 / 4 + 255) / 256, 256>>>(proj_w, 256 * 256 / 4, 1);
    gemm_mma<0><<<dim3(6, MTOT / 128), 256, SMEM_BYTES>>>(qkv_b, nullptr);
    attn_kernel<<<BWIN * NH, 64>>>();
    gemm_mma<1><<<dim3(2, MTOT / 128), 256, SMEM_BYTES>>>(proj_b, out);
}

// round 6
// speedup vs baseline: 1.4859x; 1.4859x over previous
#include <cuda_runtime.h>
#include <cuda_bf16.h>
#include <cstdint>

#define BWIN 4096
#define NTOK 49
#define DIM  256
#define NH   8
#define HD   32
#define MTOT (BWIN * NTOK)            /* 200704 */
#define QKV_S (BWIN * NH * NTOK * HD) /* 51380224 */

typedef unsigned long long u64;
typedef unsigned int u32;

// ---------------- device scratch (allocation-free) ----------------
__device__ float g_qkv[3ULL * QKV_S];                       // fp32 [3][B][H][N][hd]
__device__ float g_bias[NH * NTOK * NTOK];                  // [H][N][N]
__device__ __align__(16) __nv_bfloat16 g_xhi[(size_t)MTOT * DIM];
__device__ __align__(16) __nv_bfloat16 g_xlo[(size_t)MTOT * DIM];
__device__ __align__(16) __nv_bfloat16 g_ahi[(size_t)MTOT * DIM];
__device__ __align__(16) __nv_bfloat16 g_alo[(size_t)MTOT * DIM];
__device__ __align__(16) __nv_bfloat16 g_wqhi[768 * 256], g_wqlo[768 * 256];
__device__ __align__(16) __nv_bfloat16 g_wphi[256 * 256], g_wplo[256 * 256];

// ---------------- helpers ----------------
__device__ __forceinline__ u64 f2fma(u64 a, u64 b, u64 c) {
    u64 d;
    asm("fma.rn.f32x2 %0, %1, %2, %3;" : "=l"(d) : "l"(a), "l"(b), "l"(c));
    return d;
}
__device__ __forceinline__ u64 dup32(float x) {
    u64 d;
    asm("mov.b64 %0, {%1, %1};" : "=l"(d) : "r"(__float_as_uint(x)));
    return d;
}
__device__ __forceinline__ void split_bf(float x, unsigned short& h, unsigned short& l) {
    __nv_bfloat16 hb = __float2bfloat16(x);
    float r = x - __bfloat162float(hb);
    __nv_bfloat16 lb = __float2bfloat16(r);
    h = __bfloat16_as_ushort(hb);
    l = __bfloat16_as_ushort(lb);
}
__device__ __forceinline__ u32 smem_u32(const void* p) {
    u32 a;
    asm("{ .reg .u64 t; cvta.to.shared.u64 t, %1; cvt.u32.u64 %0, t; }" : "=r"(a) : "l"(p));
    return a;
}

__device__ __forceinline__ void mma16816(float* d, u32 a0, u32 a1, u32 a2, u32 a3,
                                         u32 b0, u32 b1) {
    asm volatile(
        "mma.sync.aligned.m16n8k16.row.col.f32.bf16.bf16.f32 "
        "{%0,%1,%2,%3}, {%4,%5,%6,%7}, {%8,%9}, {%0,%1,%2,%3};"
        : "+f"(d[0]), "+f"(d[1]), "+f"(d[2]), "+f"(d[3])
        : "r"(a0), "r"(a1), "r"(a2), "r"(a3), "r"(b0), "r"(b1));
}

#define LDSM_X4(r0, r1, r2, r3, addr) \
    asm volatile("ldmatrix.sync.aligned.m8n8.x4.shared.b16 {%0,%1,%2,%3}, [%4];" \
        : "=r"(r0), "=r"(r1), "=r"(r2), "=r"(r3) : "r"(addr))

#define CP_ASYNC16(s, g) \
    asm volatile("cp.async.cg.shared.global [%0], [%1], 16;" :: "r"(s), "l"(g))
#define CP_COMMIT() asm volatile("cp.async.commit_group;" ::: "memory")
#define CP_WAITG(n) asm volatile("cp.async.wait_group %0;" :: "n"(n) : "memory")

// ---------------- kernel: bias gather ----------------
__global__ void bias_kernel(const float* __restrict__ table, const int* __restrict__ rel) {
    int idx = blockIdx.x * 256 + threadIdx.x;
    if (idx < NH * NTOK * NTOK) {
        int h = idx / (NTOK * NTOK);
        int nm = idx - h * (NTOK * NTOK);
        g_bias[idx] = table[rel[nm] * NH + h];
    }
}

// ---------------- kernels: fp32 -> bf16 hi/lo ----------------
__global__ void conv_x(const float* __restrict__ x) {
    size_t i = (size_t)blockIdx.x * 256 + threadIdx.x;
    if (i < (size_t)MTOT * DIM / 4) {
        float4 v = ((const float4*)x)[i];
        unsigned short h0, h1, h2, h3, l0, l1, l2, l3;
        split_bf(v.x, h0, l0); split_bf(v.y, h1, l1);
        split_bf(v.z, h2, l2); split_bf(v.w, h3, l3);
        ((uint2*)g_xhi)[i] = make_uint2((u32)h0 | ((u32)h1 << 16), (u32)h2 | ((u32)h3 << 16));
        ((uint2*)g_xlo)[i] = make_uint2((u32)l0 | ((u32)l1 << 16), (u32)l2 | ((u32)l3 << 16));
    }
}
__global__ void conv_w(const float* __restrict__ w, int n4, int which) {
    int i = blockIdx.x * 256 + threadIdx.x;
    if (i < n4) {
        __nv_bfloat16* hi = which ? g_wphi : g_wqhi;
        __nv_bfloat16* lo = which ? g_wplo : g_wqlo;
        float4 v = ((const float4*)w)[i];
        unsigned short h0, h1, h2, h3, l0, l1, l2, l3;
        split_bf(v.x, h0, l0); split_bf(v.y, h1, l1);
        split_bf(v.z, h2, l2); split_bf(v.w, h3, l3);
        ((uint2*)hi)[i] = make_uint2((u32)h0 | ((u32)h1 << 16), (u32)h2 | ((u32)h3 << 16));
        ((uint2*)lo)[i] = make_uint2((u32)l0 | ((u32)l1 << 16), (u32)l2 | ((u32)l3 << 16));
    }
}

// -------- tensor-core GEMM (bf16 hi/lo, 4-stage x K16 cp.async pipeline) --------
// Stage = 24 KB, 4 stages = 96 KB -> 2 CTAs/SM retained, 3 chunk-loads in flight.
#define KC      16
#define NCHUNK  (256 / KC)                  /* 16 */
#define RSTRIDE 24                          /* elements; 48B rows, conflict-free */
#define TILE_E  (128 * RSTRIDE)
#define TILE_B  (TILE_E * 2)                /* 6144 B */
#define STAGE_B (4 * TILE_B)                /* Ah, Al, Bh, Bl = 24576 B */
#define NSTAGE  4
#define SMEM_BYTES (NSTAGE * STAGE_B)       /* 98304 */

template <int MODE>
__global__ __launch_bounds__(256)
void gemm_mma(const float* __restrict__ bias, float* __restrict__ out) {
    extern __shared__ __nv_bfloat16 sm[];

    const __nv_bfloat16* Ah = MODE ? g_ahi : g_xhi;
    const __nv_bfloat16* Al = MODE ? g_alo : g_xlo;
    const __nv_bfloat16* Bh = MODE ? g_wphi : g_wqhi;
    const __nv_bfloat16* Bl = MODE ? g_wplo : g_wqlo;

    const int tid  = threadIdx.x;
    const int warp = tid >> 5;
    const int lane = tid & 31;
    const int g    = lane >> 2;
    const int t4   = lane & 3;
    const int wm   = warp >> 2;       // 0..1
    const int wn   = warp & 3;        // 0..3

    // N-block fastest (blockIdx.x) -> concurrent CTAs share A slice in L2
    const int    o0 = blockIdx.x * 128;
    const size_t m0 = (size_t)blockIdx.y * 128;

    const u32 smem_base = smem_u32(sm);

    // gmem -> smem copy mapping: 1 x 16B per tile per thread (128 rows x 16 cols)
    const int row = tid >> 1;                  // 0..127
    const int seg = (tid & 1) * 8;             // 0 or 8

    const __nv_bfloat16* gAh = Ah + (m0 + row) * 256 + seg;
    const __nv_bfloat16* gAl = Al + (m0 + row) * 256 + seg;
    const __nv_bfloat16* gBh = Bh + (size_t)(o0 + row) * 256 + seg;
    const __nv_bfloat16* gBl = Bl + (size_t)(o0 + row) * 256 + seg;

    const u32 sb = (u32)(row * RSTRIDE + seg) * 2;

    // ldmatrix per-lane offsets (bytes, relative to stage base)
    const int q3 = (lane >> 3) & 1;
    const int q4 = (lane >> 4) & 1;
    const int r8 = lane & 7;
    const u32 offA  = 0 * TILE_B + (u32)(((wm * 64 + q3 * 8 + r8) * RSTRIDE) + q4 * 8) * 2;
    const u32 offB0 = 2 * TILE_B + (u32)(((wn * 32 + 0 * 16 + q4 * 8 + r8) * RSTRIDE) + q3 * 8) * 2;
    const u32 offB1 = 2 * TILE_B + (u32)(((wn * 32 + 1 * 16 + q4 * 8 + r8) * RSTRIDE) + q3 * 8) * 2;

    float acc[4][4][4];
#pragma unroll
    for (int a = 0; a < 4; ++a)
#pragma unroll
        for (int b = 0; b < 4; ++b)
#pragma unroll
            for (int c = 0; c < 4; ++c) acc[a][b][c] = 0.f;

#define ISSUE_STAGE(stg, kb) do {                                  \
        const u32 nx = smem_base + (u32)(stg) * STAGE_B;           \
        CP_ASYNC16(nx + 0 * TILE_B + sb, gAh + (kb));              \
        CP_ASYNC16(nx + 1 * TILE_B + sb, gAl + (kb));              \
        CP_ASYNC16(nx + 2 * TILE_B + sb, gBh + (kb));              \
        CP_ASYNC16(nx + 3 * TILE_B + sb, gBl + (kb));              \
        CP_COMMIT();                                               \
    } while (0)

    // ---- prologue: stages 0..2 ----
    ISSUE_STAGE(0, 0);
    ISSUE_STAGE(1, KC);
    ISSUE_STAGE(2, 2 * KC);

#pragma unroll 1
    for (int kc = 0; kc < NCHUNK; ++kc) {
        if (kc < NCHUNK - 2)       CP_WAITG(2);
        else if (kc == NCHUNK - 2) CP_WAITG(1);
        else                       CP_WAITG(0);
        __syncthreads();

        if (kc + 3 < NCHUNK) ISSUE_STAGE((kc + 3) & 3, (kc + 3) * KC);

        const u32 stb = smem_base + (u32)(kc & 3) * STAGE_B;
        u32 bh[4][2], bl[4][2];
        LDSM_X4(bh[0][0], bh[0][1], bh[1][0], bh[1][1], stb + offB0);
        LDSM_X4(bh[2][0], bh[2][1], bh[3][0], bh[3][1], stb + offB1);
        LDSM_X4(bl[0][0], bl[0][1], bl[1][0], bl[1][1], stb + offB0 + TILE_B);
        LDSM_X4(bl[2][0], bl[2][1], bl[3][0], bl[3][1], stb + offB1 + TILE_B);
#pragma unroll
        for (int mi = 0; mi < 4; ++mi) {
            const u32 ao = stb + offA + (u32)(mi * 16 * RSTRIDE * 2);
            u32 ah0, ah1, ah2, ah3, al0, al1, al2, al3;
            LDSM_X4(ah0, ah1, ah2, ah3, ao);
            LDSM_X4(al0, al1, al2, al3, ao + TILE_B);
#pragma unroll
            for (int ni = 0; ni < 4; ++ni) {
                mma16816(acc[mi][ni], ah0, ah1, ah2, ah3, bh[ni][0], bh[ni][1]);
                mma16816(acc[mi][ni], al0, al1, al2, al3, bh[ni][0], bh[ni][1]);
                mma16816(acc[mi][ni], ah0, ah1, ah2, ah3, bl[ni][0], bl[ni][1]);
            }
        }
    }
#undef ISSUE_STAGE

    // ---- epilogue: bias add + store straight from registers ----
#pragma unroll
    for (int mi = 0; mi < 4; ++mi) {
        const int r0 = (int)m0 + wm * 64 + mi * 16 + g;
        const int r1 = r0 + 8;
#pragma unroll
        for (int ni = 0; ni < 4; ++ni) {
            const int c = o0 + wn * 32 + ni * 8 + 2 * t4;
            const float b0 = bias[c], b1 = bias[c + 1];
            float v00 = acc[mi][ni][0] + b0, v01 = acc[mi][ni][1] + b1;
            float v10 = acc[mi][ni][2] + b0, v11 = acc[mi][ni][3] + b1;
            if (MODE == 0) {
                const int which = c >> 8;
                const int head  = (c >> 5) & 7;
                const int d     = c & 31;
#pragma unroll
                for (int rr = 0; rr < 2; ++rr) {
                    const int m = rr ? r1 : r0;
                    const int bwin = m / NTOK;
                    const int n = m - bwin * NTOK;
                    float* dst = g_qkv + (size_t)which * QKV_S +
                        (((size_t)bwin * NH + head) * NTOK + n) * HD + d;
                    *(float2*)dst = rr ? make_float2(v10, v11) : make_float2(v00, v01);
                }
            } else {
                *(float2*)(out + (size_t)r0 * 256 + c) = make_float2(v00, v01);
                *(float2*)(out + (size_t)r1 * 256 + c) = make_float2(v10, v11);
            }
        }
    }
}

// ---------------- fused window attention (f32x2 register tiles) ----------------
__global__ __launch_bounds__(64)
void attn_kernel() {
    __shared__ __align__(16) float sq[NTOK][34], sk[NTOK][34], sv[NTOK][34];
    __shared__ float s[NTOK][50];

    const int tid = threadIdx.x;
    const int bh = blockIdx.x;
    const int bwin = bh >> 3;
    const int h = bh & 7;

    const size_t base = (size_t)bh * (NTOK * HD);
    const float4* q4 = (const float4*)(g_qkv + base);
    const float4* k4 = (const float4*)(g_qkv + (size_t)QKV_S + base);
    const float4* v4 = (const float4*)(g_qkv + 2ULL * QKV_S + base);

    for (int i = tid; i < NTOK * HD / 4; i += 64) {
        const int r = i >> 3, c = (i & 7) * 4;
        float4 a = q4[i];
        sq[r][c] = a.x; sq[r][c + 1] = a.y; sq[r][c + 2] = a.z; sq[r][c + 3] = a.w;
        float4 b = k4[i];
        sk[r][c] = b.x; sk[r][c + 1] = b.y; sk[r][c + 2] = b.z; sk[r][c + 3] = b.w;
        float4 d = v4[i];
        sv[r][c] = d.x; sv[r][c + 1] = d.y; sv[r][c + 2] = d.z; sv[r][c + 3] = d.w;
    }
    __syncthreads();

    if (tid < 49) {
        const int ti = tid / 7, tj = tid - ti * 7;
        const int n0 = ti * 7, m0 = tj * 7;
        u64 acc[7][7];
#pragma unroll
        for (int r = 0; r < 7; ++r)
#pragma unroll
            for (int cc = 0; cc < 7; ++cc) acc[r][cc] = 0ull;
#pragma unroll
        for (int kk = 0; kk < 16; ++kk) {
            u64 qv[7], kv[7];
#pragma unroll
            for (int r = 0; r < 7; ++r) qv[r] = *(const u64*)&sq[n0 + r][2 * kk];
#pragma unroll
            for (int cc = 0; cc < 7; ++cc) kv[cc] = *(const u64*)&sk[m0 + cc][2 * kk];
#pragma unroll
            for (int r = 0; r < 7; ++r)
#pragma unroll
                for (int cc = 0; cc < 7; ++cc) acc[r][cc] = f2fma(qv[r], kv[cc], acc[r][cc]);
        }
        const float scale = 0.17677669529663687f;
        const float* bb = g_bias + h * (NTOK * NTOK);
#pragma unroll
        for (int r = 0; r < 7; ++r)
#pragma unroll
            for (int cc = 0; cc < 7; ++cc) {
                const u64 a = acc[r][cc];
                const float lo = __uint_as_float((u32)(a & 0xffffffffull));
                const float hi = __uint_as_float((u32)(a >> 32));
                s[n0 + r][m0 + cc] = (lo + hi) * scale + bb[(n0 + r) * NTOK + m0 + cc];
            }
    }
    __syncthreads();

    if (tid < 49) {
        float mx = -1e30f;
#pragma unroll
        for (int c = 0; c < NTOK; ++c) mx = fmaxf(mx, s[tid][c]);
        float sum = 0.f;
#pragma unroll
        for (int c = 0; c < NTOK; ++c) {
            float e = __expf(s[tid][c] - mx);
            s[tid][c] = e;
            sum += e;
        }
        const float inv = 1.f / sum;
#pragma unroll
        for (int c = 0; c < NTOK; ++c) s[tid][c] *= inv;
    }
    __syncthreads();

    // P @ V: 56 threads (2 warps), 7(n) x 4(d) register tiles, f32x2 along d
    if (tid < 56) {
        const int ti = tid >> 3, tj = tid & 7;     // 7 n-groups x 8 d-groups
        const int n0 = ti * 7, d0 = tj * 4;
        u64 acc2[7][2];
#pragma unroll
        for (int r = 0; r < 7; ++r) { acc2[r][0] = 0ull; acc2[r][1] = 0ull; }
#pragma unroll 7
        for (int m = 0; m < NTOK; ++m) {
            const u64 v0 = *(const u64*)&sv[m][d0];
            const u64 v1 = *(const u64*)&sv[m][d0 + 2];
#pragma unroll
            for (int r = 0; r < 7; ++r) {
                const u64 sd = dup32(s[n0 + r][m]);
                acc2[r][0] = f2fma(sd, v0, acc2[r][0]);
                acc2[r][1] = f2fma(sd, v1, acc2[r][1]);
            }
        }
#pragma unroll
        for (int r = 0; r < 7; ++r) {
            unsigned short hh[4], ll[4];
#pragma unroll
            for (int cc = 0; cc < 2; ++cc) {
                const u64 a = acc2[r][cc];
                split_bf(__uint_as_float((u32)(a & 0xffffffffull)), hh[2 * cc], ll[2 * cc]);
                split_bf(__uint_as_float((u32)(a >> 32)), hh[2 * cc + 1], ll[2 * cc + 1]);
            }
            uint2 vh = make_uint2((u32)hh[0] | ((u32)hh[1] << 16), (u32)hh[2] | ((u32)hh[3] << 16));
            uint2 vl = make_uint2((u32)ll[0] | ((u32)ll[1] << 16), (u32)ll[2] | ((u32)ll[3] << 16));
            const size_t off = ((size_t)bwin * NTOK + n0 + r) * 256 + h * 32 + d0;
            *(uint2*)(g_ahi + off) = vh;
            *(uint2*)(g_alo + off) = vl;
        }
    }
}

// ---------------- launch ----------------
extern "C" void kernel_launch(void* const* d_in, const int* in_sizes, int n_in,
                              void* d_out, int out_size) {
    const float* x      = (const float*)d_in[0];
    const float* qkv_w  = (const float*)d_in[1];
    const float* qkv_b  = (const float*)d_in[2];
    const float* proj_w = (const float*)d_in[3];
    const float* proj_b = (const float*)d_in[4];
    const float* table  = (const float*)d_in[5];
    const int*   rel    = (const int*)d_in[6];
    float* out = (float*)d_out;

    static int smem_set = 0;
    if (!smem_set) {
        cudaFuncSetAttribute(gemm_mma<0>, cudaFuncAttributeMaxDynamicSharedMemorySize, SMEM_BYTES);
        cudaFuncSetAttribute(gemm_mma<1>, cudaFuncAttributeMaxDynamicSharedMemorySize, SMEM_BYTES);
        smem_set = 1;
    }

    bias_kernel<<<(NH * NTOK * NTOK + 255) / 256, 256>>>(table, rel);
    conv_x<<<(int)(((size_t)MTOT * DIM / 4 + 255) / 256), 256>>>(x);
    conv_w<<<(768 * 256 / 4 + 255) / 256, 256>>>(qkv_w, 768 * 256 / 4, 0);
    conv_w<<<(256 * 256 / 4 + 255) / 256, 256>>>(proj_w, 256 * 256 / 4, 1);
    gemm_mma<0><<<dim3(6, MTOT / 128), 256, SMEM_BYTES>>>(qkv_b, nullptr);
    attn_kernel<<<BWIN * NH, 64>>>();
    gemm_mma<1><<<dim3(2, MTOT / 128), 256, SMEM_BYTES>>>(proj_b, out);
}

// round 7
// speedup vs baseline: 1.8623x; 1.2533x over previous
#include <cuda_runtime.h>
#include <cuda_fp16.h>
#include <cstdint>

#define BWIN 4096
#define NTOK 49
#define DIM  256
#define NH   8
#define HD   32
#define MTOT (BWIN * NTOK)            /* 200704 */
#define QKV_S (BWIN * NH * NTOK * HD) /* 51380224 */

typedef unsigned long long u64;
typedef unsigned int u32;

// ---------------- device scratch (allocation-free) ----------------
__device__ float g_qkv[3ULL * QKV_S];                       // fp32 [3][B][H][N][hd]
__device__ float g_bias[NH * NTOK * NTOK];                  // [H][N][N]
__device__ __align__(16) __half g_xhi[(size_t)MTOT * DIM];
__device__ __align__(16) __half g_xlo[(size_t)MTOT * DIM];
__device__ __align__(16) __half g_ahi[(size_t)MTOT * DIM];
__device__ __align__(16) __half g_alo[(size_t)MTOT * DIM];
__device__ __align__(16) __half g_wqhi[768 * 256], g_wqlo[768 * 256];
__device__ __align__(16) __half g_wphi[256 * 256], g_wplo[256 * 256];

// ---------------- helpers ----------------
__device__ __forceinline__ u64 f2fma(u64 a, u64 b, u64 c) {
    u64 d;
    asm("fma.rn.f32x2 %0, %1, %2, %3;" : "=l"(d) : "l"(a), "l"(b), "l"(c));
    return d;
}
__device__ __forceinline__ u64 dup32(float x) {
    u64 d;
    asm("mov.b64 %0, {%1, %1};" : "=l"(d) : "r"(__float_as_uint(x)));
    return d;
}
__device__ __forceinline__ void split_h(float x, unsigned short& h, unsigned short& l) {
    __half hb = __float2half_rn(x);
    float r = x - __half2float(hb);
    __half lb = __float2half_rn(r);
    h = __half_as_ushort(hb);
    l = __half_as_ushort(lb);
}
__device__ __forceinline__ u32 smem_u32(const void* p) {
    u32 a;
    asm("{ .reg .u64 t; cvta.to.shared.u64 t, %1; cvt.u32.u64 %0, t; }" : "=r"(a) : "l"(p));
    return a;
}

__device__ __forceinline__ void mma16816(float* d, u32 a0, u32 a1, u32 a2, u32 a3,
                                         u32 b0, u32 b1) {
    asm volatile(
        "mma.sync.aligned.m16n8k16.row.col.f32.f16.f16.f32 "
        "{%0,%1,%2,%3}, {%4,%5,%6,%7}, {%8,%9}, {%0,%1,%2,%3};"
        : "+f"(d[0]), "+f"(d[1]), "+f"(d[2]), "+f"(d[3])
        : "r"(a0), "r"(a1), "r"(a2), "r"(a3), "r"(b0), "r"(b1));
}

#define LDSM_X4(r0, r1, r2, r3, addr) \
    asm volatile("ldmatrix.sync.aligned.m8n8.x4.shared.b16 {%0,%1,%2,%3}, [%4];" \
        : "=r"(r0), "=r"(r1), "=r"(r2), "=r"(r3) : "r"(addr))

#define CP_ASYNC16(s, g) \
    asm volatile("cp.async.cg.shared.global [%0], [%1], 16;" :: "r"(s), "l"(g))
#define CP_COMMIT() asm volatile("cp.async.commit_group;" ::: "memory")
#define CP_WAIT0()  asm volatile("cp.async.wait_group 0;" ::: "memory")

// ---------------- kernel: bias gather ----------------
__global__ void bias_kernel(const float* __restrict__ table, const int* __restrict__ rel) {
    int idx = blockIdx.x * 256 + threadIdx.x;
    if (idx < NH * NTOK * NTOK) {
        int h = idx / (NTOK * NTOK);
        int nm = idx - h * (NTOK * NTOK);
        g_bias[idx] = table[rel[nm] * NH + h];
    }
}

// ---------------- kernels: fp32 -> fp16 hi/lo ----------------
__global__ void conv_x(const float* __restrict__ x) {
    size_t i = (size_t)blockIdx.x * 256 + threadIdx.x;
    if (i < (size_t)MTOT * DIM / 4) {
        float4 v = ((const float4*)x)[i];
        unsigned short h0, h1, h2, h3, l0, l1, l2, l3;
        split_h(v.x, h0, l0); split_h(v.y, h1, l1);
        split_h(v.z, h2, l2); split_h(v.w, h3, l3);
        ((uint2*)g_xhi)[i] = make_uint2((u32)h0 | ((u32)h1 << 16), (u32)h2 | ((u32)h3 << 16));
        ((uint2*)g_xlo)[i] = make_uint2((u32)l0 | ((u32)l1 << 16), (u32)l2 | ((u32)l3 << 16));
    }
}
__global__ void conv_w(const float* __restrict__ w, int n4, int which) {
    int i = blockIdx.x * 256 + threadIdx.x;
    if (i < n4) {
        __half* hi = which ? g_wphi : g_wqhi;
        __half* lo = which ? g_wplo : g_wqlo;
        float4 v = ((const float4*)w)[i];
        unsigned short h0, h1, h2, h3, l0, l1, l2, l3;
        split_h(v.x, h0, l0); split_h(v.y, h1, l1);
        split_h(v.z, h2, l2); split_h(v.w, h3, l3);
        ((uint2*)hi)[i] = make_uint2((u32)h0 | ((u32)h1 << 16), (u32)h2 | ((u32)h3 << 16));
        ((uint2*)lo)[i] = make_uint2((u32)l0 | ((u32)l1 << 16), (u32)l2 | ((u32)l3 << 16));
    }
}

// -------- tensor-core GEMM (fp16 hi/lo, R4-proven K32 2-stage pipeline) --------
// NTERMS=3: Ah*Bh + Al*Bh + Ah*Bl (tiles Ah,Al,Bh,Bl; stage 40KB)
// NTERMS=2: Ah*Bh + Al*Bh          (tiles Ah,Al,Bh;    stage 30KB)
#define KC      32
#define RSTRIDE 40                          /* elements; 80B rows, conflict-free */
#define TILE_E  (128 * RSTRIDE)
#define TILE_B  (TILE_E * 2)                /* 10240 B */

template <int MODE, int NTERMS>
__global__ __launch_bounds__(256)
void gemm_mma(const float* __restrict__ bias, float* __restrict__ out, int o_base) {
    constexpr int NTILES  = NTERMS + 1;
    constexpr int STAGE_B = NTILES * TILE_B;
    extern __shared__ __half sm[];

    const __half* Ah = MODE ? g_ahi : g_xhi;
    const __half* Al = MODE ? g_alo : g_xlo;
    const __half* Bh = MODE ? g_wphi : g_wqhi;
    const __half* Bl = MODE ? g_wplo : g_wqlo;

    const int tid  = threadIdx.x;
    const int warp = tid >> 5;
    const int lane = tid & 31;
    const int g    = lane >> 2;
    const int t4   = lane & 3;
    const int wm   = warp >> 2;       // 0..1
    const int wn   = warp & 3;        // 0..3

    // N-block fastest -> concurrent CTAs share A slice in L2
    const int    o0 = o_base + blockIdx.x * 128;
    const size_t m0 = (size_t)blockIdx.y * 128;

    const u32 smem_base = smem_u32(sm);

    // gmem -> smem copy mapping: 2 x 16B per tile per thread
    const int row0 = tid >> 2;
    const int row1 = row0 + 64;
    const int seg  = (tid & 3) * 8;

    const __half* gA0h = Ah + (m0 + row0) * 256 + seg;
    const __half* gA1h = Ah + (m0 + row1) * 256 + seg;
    const __half* gA0l = Al + (m0 + row0) * 256 + seg;
    const __half* gA1l = Al + (m0 + row1) * 256 + seg;
    const __half* gB0h = Bh + (size_t)(o0 + row0) * 256 + seg;
    const __half* gB1h = Bh + (size_t)(o0 + row1) * 256 + seg;
    const __half* gB0l = Bl + (size_t)(o0 + row0) * 256 + seg;
    const __half* gB1l = Bl + (size_t)(o0 + row1) * 256 + seg;

    const u32 s0b = (u32)(row0 * RSTRIDE + seg) * 2;
    const u32 s1b = (u32)(row1 * RSTRIDE + seg) * 2;

    // ldmatrix per-lane offsets (bytes, relative to stage base)
    const int q3 = (lane >> 3) & 1;
    const int q4 = (lane >> 4) & 1;
    const int r8 = lane & 7;
    const u32 offA  = 0 * TILE_B + (u32)(((wm * 64 + q3 * 8 + r8) * RSTRIDE) + q4 * 8) * 2;
    const u32 offB0 = 2 * TILE_B + (u32)(((wn * 32 + 0 * 16 + q4 * 8 + r8) * RSTRIDE) + q3 * 8) * 2;
    const u32 offB1 = 2 * TILE_B + (u32)(((wn * 32 + 1 * 16 + q4 * 8 + r8) * RSTRIDE) + q3 * 8) * 2;

    float acc[4][4][4];
#pragma unroll
    for (int a = 0; a < 4; ++a)
#pragma unroll
        for (int b = 0; b < 4; ++b)
#pragma unroll
            for (int c = 0; c < 4; ++c) acc[a][b][c] = 0.f;

#define ISSUE_STAGE(stg, kb) do {                                      \
        const u32 nx = smem_base + (u32)(stg) * STAGE_B;               \
        CP_ASYNC16(nx + 0 * TILE_B + s0b, gA0h + (kb));                \
        CP_ASYNC16(nx + 0 * TILE_B + s1b, gA1h + (kb));                \
        CP_ASYNC16(nx + 1 * TILE_B + s0b, gA0l + (kb));                \
        CP_ASYNC16(nx + 1 * TILE_B + s1b, gA1l + (kb));                \
        CP_ASYNC16(nx + 2 * TILE_B + s0b, gB0h + (kb));                \
        CP_ASYNC16(nx + 2 * TILE_B + s1b, gB1h + (kb));                \
        if (NTERMS == 3) {                                             \
            CP_ASYNC16(nx + 3 * TILE_B + s0b, gB0l + (kb));            \
            CP_ASYNC16(nx + 3 * TILE_B + s1b, gB1l + (kb));            \
        }                                                              \
        CP_COMMIT();                                                   \
    } while (0)

    // ---- prologue ----
    ISSUE_STAGE(0, 0);
    CP_WAIT0();
    __syncthreads();

#pragma unroll 1
    for (int kc = 0; kc < 8; ++kc) {
        const int cur = kc & 1;
        const u32 stb = smem_base + (u32)cur * STAGE_B;

        if (kc < 7) ISSUE_STAGE(cur ^ 1, (kc + 1) * KC);

#pragma unroll
        for (int ks = 0; ks < 2; ++ks) {
            const u32 kso = (u32)(ks * 32);
            u32 bh[4][2], bl[4][2];
            LDSM_X4(bh[0][0], bh[0][1], bh[1][0], bh[1][1], stb + offB0 + kso);
            LDSM_X4(bh[2][0], bh[2][1], bh[3][0], bh[3][1], stb + offB1 + kso);
            if (NTERMS == 3) {
                LDSM_X4(bl[0][0], bl[0][1], bl[1][0], bl[1][1], stb + offB0 + TILE_B + kso);
                LDSM_X4(bl[2][0], bl[2][1], bl[3][0], bl[3][1], stb + offB1 + TILE_B + kso);
            }
#pragma unroll
            for (int mi = 0; mi < 4; ++mi) {
                const u32 ao = stb + offA + (u32)(mi * 16 * RSTRIDE * 2) + kso;
                u32 ah0, ah1, ah2, ah3, al0, al1, al2, al3;
                LDSM_X4(ah0, ah1, ah2, ah3, ao);
                LDSM_X4(al0, al1, al2, al3, ao + TILE_B);
#pragma unroll
                for (int ni = 0; ni < 4; ++ni) {
                    mma16816(acc[mi][ni], ah0, ah1, ah2, ah3, bh[ni][0], bh[ni][1]);
                    mma16816(acc[mi][ni], al0, al1, al2, al3, bh[ni][0], bh[ni][1]);
                    if (NTERMS == 3)
                        mma16816(acc[mi][ni], ah0, ah1, ah2, ah3, bl[ni][0], bl[ni][1]);
                }
            }
        }

        if (kc < 7) CP_WAIT0();
        __syncthreads();
    }
#undef ISSUE_STAGE

    // ---- epilogue: bias add + store straight from registers ----
#pragma unroll
    for (int mi = 0; mi < 4; ++mi) {
        const int r0 = (int)m0 + wm * 64 + mi * 16 + g;
        const int r1 = r0 + 8;
#pragma unroll
        for (int ni = 0; ni < 4; ++ni) {
            const int c = o0 + wn * 32 + ni * 8 + 2 * t4;
            const float b0 = bias[c], b1 = bias[c + 1];
            float v00 = acc[mi][ni][0] + b0, v01 = acc[mi][ni][1] + b1;
            float v10 = acc[mi][ni][2] + b0, v11 = acc[mi][ni][3] + b1;
            if (MODE == 0) {
                const int which = c >> 8;
                const int head  = (c >> 5) & 7;
                const int d     = c & 31;
#pragma unroll
                for (int rr = 0; rr < 2; ++rr) {
                    const int m = rr ? r1 : r0;
                    const int bwin = m / NTOK;
                    const int n = m - bwin * NTOK;
                    float* dst = g_qkv + (size_t)which * QKV_S +
                        (((size_t)bwin * NH + head) * NTOK + n) * HD + d;
                    *(float2*)dst = rr ? make_float2(v10, v11) : make_float2(v00, v01);
                }
            } else {
                *(float2*)(out + (size_t)r0 * 256 + c) = make_float2(v00, v01);
                *(float2*)(out + (size_t)r1 * 256 + c) = make_float2(v10, v11);
            }
        }
    }
}

// ---------------- fused window attention (f32x2 register tiles) ----------------
__global__ __launch_bounds__(64)
void attn_kernel() {
    __shared__ __align__(16) float sq[NTOK][34], sk[NTOK][34], sv[NTOK][34];
    __shared__ float s[NTOK][50];

    const int tid = threadIdx.x;
    const int bh = blockIdx.x;
    const int bwin = bh >> 3;
    const int h = bh & 7;

    const size_t base = (size_t)bh * (NTOK * HD);
    const float4* q4 = (const float4*)(g_qkv + base);
    const float4* k4 = (const float4*)(g_qkv + (size_t)QKV_S + base);
    const float4* v4 = (const float4*)(g_qkv + 2ULL * QKV_S + base);

    for (int i = tid; i < NTOK * HD / 4; i += 64) {
        const int r = i >> 3, c = (i & 7) * 4;
        float4 a = q4[i];
        sq[r][c] = a.x; sq[r][c + 1] = a.y; sq[r][c + 2] = a.z; sq[r][c + 3] = a.w;
        float4 b = k4[i];
        sk[r][c] = b.x; sk[r][c + 1] = b.y; sk[r][c + 2] = b.z; sk[r][c + 3] = b.w;
        float4 d = v4[i];
        sv[r][c] = d.x; sv[r][c + 1] = d.y; sv[r][c + 2] = d.z; sv[r][c + 3] = d.w;
    }
    __syncthreads();

    if (tid < 49) {
        const int ti = tid / 7, tj = tid - ti * 7;
        const int n0 = ti * 7, m0 = tj * 7;
        u64 acc[7][7];
#pragma unroll
        for (int r = 0; r < 7; ++r)
#pragma unroll
            for (int cc = 0; cc < 7; ++cc) acc[r][cc] = 0ull;
#pragma unroll
        for (int kk = 0; kk < 16; ++kk) {
            u64 qv[7], kv[7];
#pragma unroll
            for (int r = 0; r < 7; ++r) qv[r] = *(const u64*)&sq[n0 + r][2 * kk];
#pragma unroll
            for (int cc = 0; cc < 7; ++cc) kv[cc] = *(const u64*)&sk[m0 + cc][2 * kk];
#pragma unroll
            for (int r = 0; r < 7; ++r)
#pragma unroll
                for (int cc = 0; cc < 7; ++cc) acc[r][cc] = f2fma(qv[r], kv[cc], acc[r][cc]);
        }
        const float scale = 0.17677669529663687f;
        const float* bb = g_bias + h * (NTOK * NTOK);
#pragma unroll
        for (int r = 0; r < 7; ++r)
#pragma unroll
            for (int cc = 0; cc < 7; ++cc) {
                const u64 a = acc[r][cc];
                const float lo = __uint_as_float((u32)(a & 0xffffffffull));
                const float hi = __uint_as_float((u32)(a >> 32));
                s[n0 + r][m0 + cc] = (lo + hi) * scale + bb[(n0 + r) * NTOK + m0 + cc];
            }
    }
    __syncthreads();

    if (tid < 49) {
        float mx = -1e30f;
#pragma unroll
        for (int c = 0; c < NTOK; ++c) mx = fmaxf(mx, s[tid][c]);
        float sum = 0.f;
#pragma unroll
        for (int c = 0; c < NTOK; ++c) {
            float e = __expf(s[tid][c] - mx);
            s[tid][c] = e;
            sum += e;
        }
        const float inv = 1.f / sum;
#pragma unroll
        for (int c = 0; c < NTOK; ++c) s[tid][c] *= inv;
    }
    __syncthreads();

    // P @ V: 56 threads (2 warps), 7(n) x 4(d) register tiles, f32x2 along d
    if (tid < 56) {
        const int ti = tid >> 3, tj = tid & 7;     // 7 n-groups x 8 d-groups
        const int n0 = ti * 7, d0 = tj * 4;
        u64 acc2[7][2];
#pragma unroll
        for (int r = 0; r < 7; ++r) { acc2[r][0] = 0ull; acc2[r][1] = 0ull; }
#pragma unroll 7
        for (int m = 0; m < NTOK; ++m) {
            const u64 v0 = *(const u64*)&sv[m][d0];
            const u64 v1 = *(const u64*)&sv[m][d0 + 2];
#pragma unroll
            for (int r = 0; r < 7; ++r) {
                const u64 sd = dup32(s[n0 + r][m]);
                acc2[r][0] = f2fma(sd, v0, acc2[r][0]);
                acc2[r][1] = f2fma(sd, v1, acc2[r][1]);
            }
        }
#pragma unroll
        for (int r = 0; r < 7; ++r) {
            unsigned short hh[4], ll[4];
#pragma unroll
            for (int cc = 0; cc < 2; ++cc) {
                const u64 a = acc2[r][cc];
                split_h(__uint_as_float((u32)(a & 0xffffffffull)), hh[2 * cc], ll[2 * cc]);
                split_h(__uint_as_float((u32)(a >> 32)), hh[2 * cc + 1], ll[2 * cc + 1]);
            }
            uint2 vh = make_uint2((u32)hh[0] | ((u32)hh[1] << 16), (u32)hh[2] | ((u32)hh[3] << 16));
            uint2 vl = make_uint2((u32)ll[0] | ((u32)ll[1] << 16), (u32)ll[2] | ((u32)ll[3] << 16));
            const size_t off = ((size_t)bwin * NTOK + n0 + r) * 256 + h * 32 + d0;
            *(uint2*)(g_ahi + off) = vh;
            *(uint2*)(g_alo + off) = vl;
        }
    }
}

// ---------------- launch ----------------
extern "C" void kernel_launch(void* const* d_in, const int* in_sizes, int n_in,
                              void* d_out, int out_size) {
    const float* x      = (const float*)d_in[0];
    const float* qkv_w  = (const float*)d_in[1];
    const float* qkv_b  = (const float*)d_in[2];
    const float* proj_w = (const float*)d_in[3];
    const float* proj_b = (const float*)d_in[4];
    const float* table  = (const float*)d_in[5];
    const int*   rel    = (const int*)d_in[6];
    float* out = (float*)d_out;

    const int SM3 = 2 * 4 * TILE_B;   // 81920
    const int SM2 = 2 * 3 * TILE_B;   // 61440

    static int smem_set = 0;
    if (!smem_set) {
        cudaFuncSetAttribute(gemm_mma<0, 3>, cudaFuncAttributeMaxDynamicSharedMemorySize, SM3);
        cudaFuncSetAttribute(gemm_mma<0, 2>, cudaFuncAttributeMaxDynamicSharedMemorySize, SM2);
        cudaFuncSetAttribute(gemm_mma<1, 2>, cudaFuncAttributeMaxDynamicSharedMemorySize, SM2);
        smem_set = 1;
    }

    bias_kernel<<<(NH * NTOK * NTOK + 255) / 256, 256>>>(table, rel);
    conv_x<<<(int)(((size_t)MTOT * DIM / 4 + 255) / 256), 256>>>(x);
    conv_w<<<(768 * 256 / 4 + 255) / 256, 256>>>(qkv_w, 768 * 256 / 4, 0);
    conv_w<<<(256 * 256 / 4 + 255) / 256, 256>>>(proj_w, 256 * 256 / 4, 1);
    // Q,K columns: 3-term (exact logits). V columns: 2-term. Proj: 2-term.
    gemm_mma<0, 3><<<dim3(4, MTOT / 128), 256, SM3>>>(qkv_b, nullptr, 0);
    gemm_mma<0, 2><<<dim3(2, MTOT / 128), 256, SM2>>>(qkv_b, nullptr, 512);
    attn_kernel<<<BWIN * NH, 64>>>();
    gemm_mma<1, 2><<<dim3(2, MTOT / 128), 256, SM2>>>(proj_b, out, 0);
}

// round 8
// speedup vs baseline: 2.0784x; 1.1160x over previous
#include <cuda_runtime.h>
#include <cuda_fp16.h>
#include <cstdint>

#define BWIN 4096
#define NTOK 49
#define DIM  256
#define NH   8
#define HD   32
#define MTOT (BWIN * NTOK)            /* 200704 */
#define QKV_S (BWIN * NH * NTOK * HD) /* 51380224 */

typedef unsigned long long u64;
typedef unsigned int u32;

// ---------------- device scratch (allocation-free) ----------------
__device__ float g_qkv[3ULL * QKV_S];                       // fp32 [3][B][H][N][hd]
__device__ float g_bias[NH * NTOK * NTOK];                  // [H][N][N]
__device__ __align__(16) __half g_xhi[(size_t)MTOT * DIM];
__device__ __align__(16) __half g_xlo[(size_t)MTOT * DIM];
__device__ __align__(16) __half g_ahi[(size_t)MTOT * DIM];
__device__ __align__(16) __half g_alo[(size_t)MTOT * DIM];
__device__ __align__(16) __half g_wqhi[768 * 256];
__device__ __align__(16) __half g_wphi[256 * 256];

// ---------------- helpers ----------------
__device__ __forceinline__ u64 f2fma(u64 a, u64 b, u64 c) {
    u64 d;
    asm("fma.rn.f32x2 %0, %1, %2, %3;" : "=l"(d) : "l"(a), "l"(b), "l"(c));
    return d;
}
__device__ __forceinline__ u64 dup32(float x) {
    u64 d;
    asm("mov.b64 %0, {%1, %1};" : "=l"(d) : "r"(__float_as_uint(x)));
    return d;
}
__device__ __forceinline__ void split_h(float x, unsigned short& h, unsigned short& l) {
    __half hb = __float2half_rn(x);
    float r = x - __half2float(hb);
    __half lb = __float2half_rn(r);
    h = __half_as_ushort(hb);
    l = __half_as_ushort(lb);
}
__device__ __forceinline__ u32 smem_u32(const void* p) {
    u32 a;
    asm("{ .reg .u64 t; cvta.to.shared.u64 t, %1; cvt.u32.u64 %0, t; }" : "=r"(a) : "l"(p));
    return a;
}

__device__ __forceinline__ void mma16816(float* d, u32 a0, u32 a1, u32 a2, u32 a3,
                                         u32 b0, u32 b1) {
    asm volatile(
        "mma.sync.aligned.m16n8k16.row.col.f32.f16.f16.f32 "
        "{%0,%1,%2,%3}, {%4,%5,%6,%7}, {%8,%9}, {%0,%1,%2,%3};"
        : "+f"(d[0]), "+f"(d[1]), "+f"(d[2]), "+f"(d[3])
        : "r"(a0), "r"(a1), "r"(a2), "r"(a3), "r"(b0), "r"(b1));
}

#define LDSM_X4(r0, r1, r2, r3, addr) \
    asm volatile("ldmatrix.sync.aligned.m8n8.x4.shared.b16 {%0,%1,%2,%3}, [%4];" \
        : "=r"(r0), "=r"(r1), "=r"(r2), "=r"(r3) : "r"(addr))

#define CP_ASYNC16(s, g) \
    asm volatile("cp.async.cg.shared.global [%0], [%1], 16;" :: "r"(s), "l"(g))
#define CP_COMMIT() asm volatile("cp.async.commit_group;" ::: "memory")
#define CP_WAIT0()  asm volatile("cp.async.wait_group 0;" ::: "memory")

// ---------------- kernel: bias gather ----------------
__global__ void bias_kernel(const float* __restrict__ table, const int* __restrict__ rel) {
    int idx = blockIdx.x * 256 + threadIdx.x;
    if (idx < NH * NTOK * NTOK) {
        int h = idx / (NTOK * NTOK);
        int nm = idx - h * (NTOK * NTOK);
        g_bias[idx] = table[rel[nm] * NH + h];
    }
}

// ---------------- kernels: fp32 -> fp16 hi/lo ----------------
__global__ void conv_x(const float* __restrict__ x) {
    size_t i = (size_t)blockIdx.x * 256 + threadIdx.x;
    if (i < (size_t)MTOT * DIM / 4) {
        float4 v = ((const float4*)x)[i];
        unsigned short h0, h1, h2, h3, l0, l1, l2, l3;
        split_h(v.x, h0, l0); split_h(v.y, h1, l1);
        split_h(v.z, h2, l2); split_h(v.w, h3, l3);
        ((uint2*)g_xhi)[i] = make_uint2((u32)h0 | ((u32)h1 << 16), (u32)h2 | ((u32)h3 << 16));
        ((uint2*)g_xlo)[i] = make_uint2((u32)l0 | ((u32)l1 << 16), (u32)l2 | ((u32)l3 << 16));
    }
}
// hi-only conversion of both weight matrices in one launch
__global__ void conv_w(const float* __restrict__ wq, const float* __restrict__ wp) {
    int i = blockIdx.x * 256 + threadIdx.x;
    const int nq4 = 768 * 256 / 4;
    const int np4 = 256 * 256 / 4;
    if (i < nq4) {
        float4 v = ((const float4*)wq)[i];
        ((uint2*)g_wqhi)[i] = make_uint2(
            (u32)__half_as_ushort(__float2half_rn(v.x)) | ((u32)__half_as_ushort(__float2half_rn(v.y)) << 16),
            (u32)__half_as_ushort(__float2half_rn(v.z)) | ((u32)__half_as_ushort(__float2half_rn(v.w)) << 16));
    } else if (i < nq4 + np4) {
        int j = i - nq4;
        float4 v = ((const float4*)wp)[j];
        ((uint2*)g_wphi)[j] = make_uint2(
            (u32)__half_as_ushort(__float2half_rn(v.x)) | ((u32)__half_as_ushort(__float2half_rn(v.y)) << 16),
            (u32)__half_as_ushort(__float2half_rn(v.z)) | ((u32)__half_as_ushort(__float2half_rn(v.w)) << 16));
    }
}

// -------- tensor-core GEMM (fp16 2-term: Ah*Bh + Al*Bh; K32 2-stage) --------
#define KC      32
#define RSTRIDE 40                          /* elements; 80B rows, conflict-free */
#define TILE_E  (128 * RSTRIDE)
#define TILE_B  (TILE_E * 2)                /* 10240 B */
#define STAGE_B (3 * TILE_B)                /* Ah, Al, Bh = 30720 B */
#define SMEM_BYTES (2 * STAGE_B)            /* 61440 */

template <int MODE>
__global__ __launch_bounds__(256)
void gemm_mma(const float* __restrict__ bias, float* __restrict__ out) {
    extern __shared__ __half sm[];

    const __half* Ah = MODE ? g_ahi : g_xhi;
    const __half* Al = MODE ? g_alo : g_xlo;
    const __half* Bh = MODE ? g_wphi : g_wqhi;

    const int tid  = threadIdx.x;
    const int warp = tid >> 5;
    const int lane = tid & 31;
    const int g    = lane >> 2;
    const int t4   = lane & 3;
    const int wm   = warp >> 2;       // 0..1
    const int wn   = warp & 3;        // 0..3

    // N-block fastest -> concurrent CTAs share A slice in L2
    const int    o0 = blockIdx.x * 128;
    const size_t m0 = (size_t)blockIdx.y * 128;

    const u32 smem_base = smem_u32(sm);

    // gmem -> smem copy mapping: 2 x 16B per tile per thread
    const int row0 = tid >> 2;
    const int row1 = row0 + 64;
    const int seg  = (tid & 3) * 8;

    const __half* gA0h = Ah + (m0 + row0) * 256 + seg;
    const __half* gA1h = Ah + (m0 + row1) * 256 + seg;
    const __half* gA0l = Al + (m0 + row0) * 256 + seg;
    const __half* gA1l = Al + (m0 + row1) * 256 + seg;
    const __half* gB0h = Bh + (size_t)(o0 + row0) * 256 + seg;
    const __half* gB1h = Bh + (size_t)(o0 + row1) * 256 + seg;

    const u32 s0b = (u32)(row0 * RSTRIDE + seg) * 2;
    const u32 s1b = (u32)(row1 * RSTRIDE + seg) * 2;

    // ldmatrix per-lane offsets (bytes, relative to stage base)
    const int q3 = (lane >> 3) & 1;
    const int q4 = (lane >> 4) & 1;
    const int r8 = lane & 7;
    const u32 offA  = 0 * TILE_B + (u32)(((wm * 64 + q3 * 8 + r8) * RSTRIDE) + q4 * 8) * 2;
    const u32 offB0 = 2 * TILE_B + (u32)(((wn * 32 + 0 * 16 + q4 * 8 + r8) * RSTRIDE) + q3 * 8) * 2;
    const u32 offB1 = 2 * TILE_B + (u32)(((wn * 32 + 1 * 16 + q4 * 8 + r8) * RSTRIDE) + q3 * 8) * 2;

    float acc[4][4][4];
#pragma unroll
    for (int a = 0; a < 4; ++a)
#pragma unroll
        for (int b = 0; b < 4; ++b)
#pragma unroll
            for (int c = 0; c < 4; ++c) acc[a][b][c] = 0.f;

#define ISSUE_STAGE(stg, kb) do {                                      \
        const u32 nx = smem_base + (u32)(stg) * STAGE_B;               \
        CP_ASYNC16(nx + 0 * TILE_B + s0b, gA0h + (kb));                \
        CP_ASYNC16(nx + 0 * TILE_B + s1b, gA1h + (kb));                \
        CP_ASYNC16(nx + 1 * TILE_B + s0b, gA0l + (kb));                \
        CP_ASYNC16(nx + 1 * TILE_B + s1b, gA1l + (kb));                \
        CP_ASYNC16(nx + 2 * TILE_B + s0b, gB0h + (kb));                \
        CP_ASYNC16(nx + 2 * TILE_B + s1b, gB1h + (kb));                \
        CP_COMMIT();                                                   \
    } while (0)

    // ---- prologue ----
    ISSUE_STAGE(0, 0);
    CP_WAIT0();
    __syncthreads();

#pragma unroll 1
    for (int kc = 0; kc < 8; ++kc) {
        const int cur = kc & 1;
        const u32 stb = smem_base + (u32)cur * STAGE_B;

        if (kc < 7) ISSUE_STAGE(cur ^ 1, (kc + 1) * KC);

#pragma unroll
        for (int ks = 0; ks < 2; ++ks) {
            const u32 kso = (u32)(ks * 32);
            u32 bh[4][2];
            LDSM_X4(bh[0][0], bh[0][1], bh[1][0], bh[1][1], stb + offB0 + kso);
            LDSM_X4(bh[2][0], bh[2][1], bh[3][0], bh[3][1], stb + offB1 + kso);
#pragma unroll
            for (int mi = 0; mi < 4; ++mi) {
                const u32 ao = stb + offA + (u32)(mi * 16 * RSTRIDE * 2) + kso;
                u32 ah0, ah1, ah2, ah3, al0, al1, al2, al3;
                LDSM_X4(ah0, ah1, ah2, ah3, ao);
                LDSM_X4(al0, al1, al2, al3, ao + TILE_B);
#pragma unroll
                for (int ni = 0; ni < 4; ++ni) {
                    mma16816(acc[mi][ni], ah0, ah1, ah2, ah3, bh[ni][0], bh[ni][1]);
                    mma16816(acc[mi][ni], al0, al1, al2, al3, bh[ni][0], bh[ni][1]);
                }
            }
        }

        if (kc < 7) CP_WAIT0();
        __syncthreads();
    }
#undef ISSUE_STAGE

    // ---- epilogue: bias add + store straight from registers ----
#pragma unroll
    for (int mi = 0; mi < 4; ++mi) {
        const int r0 = (int)m0 + wm * 64 + mi * 16 + g;
        const int r1 = r0 + 8;
#pragma unroll
        for (int ni = 0; ni < 4; ++ni) {
            const int c = o0 + wn * 32 + ni * 8 + 2 * t4;
            const float b0 = bias[c], b1 = bias[c + 1];
            float v00 = acc[mi][ni][0] + b0, v01 = acc[mi][ni][1] + b1;
            float v10 = acc[mi][ni][2] + b0, v11 = acc[mi][ni][3] + b1;
            if (MODE == 0) {
                const int which = c >> 8;
                const int head  = (c >> 5) & 7;
                const int d     = c & 31;
#pragma unroll
                for (int rr = 0; rr < 2; ++rr) {
                    const int m = rr ? r1 : r0;
                    const int bwin = m / NTOK;
                    const int n = m - bwin * NTOK;
                    float* dst = g_qkv + (size_t)which * QKV_S +
                        (((size_t)bwin * NH + head) * NTOK + n) * HD + d;
                    *(float2*)dst = rr ? make_float2(v10, v11) : make_float2(v00, v01);
                }
            } else {
                *(float2*)(out + (size_t)r0 * 256 + c) = make_float2(v00, v01);
                *(float2*)(out + (size_t)r1 * 256 + c) = make_float2(v10, v11);
            }
        }
    }
}

// ---------------- fused window attention (f32x2 register tiles) ----------------
__global__ __launch_bounds__(64)
void attn_kernel() {
    __shared__ __align__(16) float sq[NTOK][34], sk[NTOK][34], sv[NTOK][34];
    __shared__ float s[NTOK][50];

    const int tid = threadIdx.x;
    const int bh = blockIdx.x;
    const int bwin = bh >> 3;
    const int h = bh & 7;

    const size_t base = (size_t)bh * (NTOK * HD);
    const float4* q4 = (const float4*)(g_qkv + base);
    const float4* k4 = (const float4*)(g_qkv + (size_t)QKV_S + base);
    const float4* v4 = (const float4*)(g_qkv + 2ULL * QKV_S + base);

    for (int i = tid; i < NTOK * HD / 4; i += 64) {
        const int r = i >> 3, c = (i & 7) * 4;
        float4 a = q4[i];
        sq[r][c] = a.x; sq[r][c + 1] = a.y; sq[r][c + 2] = a.z; sq[r][c + 3] = a.w;
        float4 b = k4[i];
        sk[r][c] = b.x; sk[r][c + 1] = b.y; sk[r][c + 2] = b.z; sk[r][c + 3] = b.w;
        float4 d = v4[i];
        sv[r][c] = d.x; sv[r][c + 1] = d.y; sv[r][c + 2] = d.z; sv[r][c + 3] = d.w;
    }
    __syncthreads();

    if (tid < 49) {
        const int ti = tid / 7, tj = tid - ti * 7;
        const int n0 = ti * 7, m0 = tj * 7;
        u64 acc[7][7];
#pragma unroll
        for (int r = 0; r < 7; ++r)
#pragma unroll
            for (int cc = 0; cc < 7; ++cc) acc[r][cc] = 0ull;
#pragma unroll
        for (int kk = 0; kk < 16; ++kk) {
            u64 qv[7], kv[7];
#pragma unroll
            for (int r = 0; r < 7; ++r) qv[r] = *(const u64*)&sq[n0 + r][2 * kk];
#pragma unroll
            for (int cc = 0; cc < 7; ++cc) kv[cc] = *(const u64*)&sk[m0 + cc][2 * kk];
#pragma unroll
            for (int r = 0; r < 7; ++r)
#pragma unroll
                for (int cc = 0; cc < 7; ++cc) acc[r][cc] = f2fma(qv[r], kv[cc], acc[r][cc]);
        }
        const float scale = 0.17677669529663687f;
        const float* bb = g_bias + h * (NTOK * NTOK);
#pragma unroll
        for (int r = 0; r < 7; ++r)
#pragma unroll
            for (int cc = 0; cc < 7; ++cc) {
                const u64 a = acc[r][cc];
                const float lo = __uint_as_float((u32)(a & 0xffffffffull));
                const float hi = __uint_as_float((u32)(a >> 32));
                s[n0 + r][m0 + cc] = (lo + hi) * scale + bb[(n0 + r) * NTOK + m0 + cc];
            }
    }
    __syncthreads();

    if (tid < 49) {
        float mx = -1e30f;
#pragma unroll
        for (int c = 0; c < NTOK; ++c) mx = fmaxf(mx, s[tid][c]);
        float sum = 0.f;
#pragma unroll
        for (int c = 0; c < NTOK; ++c) {
            float e = __expf(s[tid][c] - mx);
            s[tid][c] = e;
            sum += e;
        }
        const float inv = 1.f / sum;
#pragma unroll
        for (int c = 0; c < NTOK; ++c) s[tid][c] *= inv;
    }
    __syncthreads();

    // P @ V: 56 threads (2 warps), 7(n) x 4(d) register tiles, f32x2 along d
    if (tid < 56) {
        const int ti = tid >> 3, tj = tid & 7;     // 7 n-groups x 8 d-groups
        const int n0 = ti * 7, d0 = tj * 4;
        u64 acc2[7][2];
#pragma unroll
        for (int r = 0; r < 7; ++r) { acc2[r][0] = 0ull; acc2[r][1] = 0ull; }
#pragma unroll 7
        for (int m = 0; m < NTOK; ++m) {
            const u64 v0 = *(const u64*)&sv[m][d0];
            const u64 v1 = *(const u64*)&sv[m][d0 + 2];
#pragma unroll
            for (int r = 0; r < 7; ++r) {
                const u64 sd = dup32(s[n0 + r][m]);
                acc2[r][0] = f2fma(sd, v0, acc2[r][0]);
                acc2[r][1] = f2fma(sd, v1, acc2[r][1]);
            }
        }
#pragma unroll
        for (int r = 0; r < 7; ++r) {
            unsigned short hh[4], ll[4];
#pragma unroll
            for (int cc = 0; cc < 2; ++cc) {
                const u64 a = acc2[r][cc];
                split_h(__uint_as_float((u32)(a & 0xffffffffull)), hh[2 * cc], ll[2 * cc]);
                split_h(__uint_as_float((u32)(a >> 32)), hh[2 * cc + 1], ll[2 * cc + 1]);
            }
            uint2 vh = make_uint2((u32)hh[0] | ((u32)hh[1] << 16), (u32)hh[2] | ((u32)hh[3] << 16));
            uint2 vl = make_uint2((u32)ll[0] | ((u32)ll[1] << 16), (u32)ll[2] | ((u32)ll[3] << 16));
            const size_t off = ((size_t)bwin * NTOK + n0 + r) * 256 + h * 32 + d0;
            *(uint2*)(g_ahi + off) = vh;
            *(uint2*)(g_alo + off) = vl;
        }
    }
}

// ---------------- launch ----------------
extern "C" void kernel_launch(void* const* d_in, const int* in_sizes, int n_in,
                              void* d_out, int out_size) {
    const float* x      = (const float*)d_in[0];
    const float* qkv_w  = (const float*)d_in[1];
    const float* qkv_b  = (const float*)d_in[2];
    const float* proj_w = (const float*)d_in[3];
    const float* proj_b = (const float*)d_in[4];
    const float* table  = (const float*)d_in[5];
    const int*   rel    = (const int*)d_in[6];
    float* out = (float*)d_out;

    static int smem_set = 0;
    if (!smem_set) {
        cudaFuncSetAttribute(gemm_mma<0>, cudaFuncAttributeMaxDynamicSharedMemorySize, SMEM_BYTES);
        cudaFuncSetAttribute(gemm_mma<1>, cudaFuncAttributeMaxDynamicSharedMemorySize, SMEM_BYTES);
        smem_set = 1;
    }

    bias_kernel<<<(NH * NTOK * NTOK + 255) / 256, 256>>>(table, rel);
    conv_x<<<(int)(((size_t)MTOT * DIM / 4 + 255) / 256), 256>>>(x);
    conv_w<<<((768 + 256) * 256 / 4 + 255) / 256, 256>>>(qkv_w, proj_w);
    gemm_mma<0><<<dim3(6, MTOT / 128), 256, SMEM_BYTES>>>(qkv_b, nullptr);
    attn_kernel<<<BWIN * NH, 64>>>();
    gemm_mma<1><<<dim3(2, MTOT / 128), 256, SMEM_BYTES>>>(proj_b, out);
}

// round 9
// speedup vs baseline: 2.0900x; 1.0056x over previous
#include <cuda_runtime.h>
#include <cuda_fp16.h>
#include <cstdint>

#define BWIN 4096
#define NTOK 49
#define DIM  256
#define NH   8
#define HD   32
#define MTOT (BWIN * NTOK)            /* 200704 */
#define QKV_S (BWIN * NH * NTOK * HD) /* 51380224 */

typedef unsigned long long u64;
typedef unsigned int u32;

// ---------------- device scratch (allocation-free) ----------------
__device__ float g_qkv[3ULL * QKV_S];                       // fp32 [3][B][H][N][hd]
__device__ float g_bias[NH * NTOK * NTOK];                  // [H][N][N]
__device__ __align__(16) __half g_xhi[(size_t)MTOT * DIM];
__device__ __align__(16) __half g_xlo[(size_t)MTOT * DIM];
__device__ __align__(16) __half g_ahi[(size_t)MTOT * DIM];
__device__ __align__(16) __half g_alo[(size_t)MTOT * DIM];
__device__ __align__(16) __half g_wqhi[768 * 256];
__device__ __align__(16) __half g_wphi[256 * 256];

// ---------------- helpers ----------------
__device__ __forceinline__ u64 f2fma(u64 a, u64 b, u64 c) {
    u64 d;
    asm("fma.rn.f32x2 %0, %1, %2, %3;" : "=l"(d) : "l"(a), "l"(b), "l"(c));
    return d;
}
__device__ __forceinline__ u64 dup32(float x) {
    u64 d;
    asm("mov.b64 %0, {%1, %1};" : "=l"(d) : "r"(__float_as_uint(x)));
    return d;
}
__device__ __forceinline__ void split_h(float x, unsigned short& h, unsigned short& l) {
    __half hb = __float2half_rn(x);
    float r = x - __half2float(hb);
    __half lb = __float2half_rn(r);
    h = __half_as_ushort(hb);
    l = __half_as_ushort(lb);
}
__device__ __forceinline__ u32 smem_u32(const void* p) {
    u32 a;
    asm("{ .reg .u64 t; cvta.to.shared.u64 t, %1; cvt.u32.u64 %0, t; }" : "=r"(a) : "l"(p));
    return a;
}

__device__ __forceinline__ void mma16816(float* d, u32 a0, u32 a1, u32 a2, u32 a3,
                                         u32 b0, u32 b1) {
    asm volatile(
        "mma.sync.aligned.m16n8k16.row.col.f32.f16.f16.f32 "
        "{%0,%1,%2,%3}, {%4,%5,%6,%7}, {%8,%9}, {%0,%1,%2,%3};"
        : "+f"(d[0]), "+f"(d[1]), "+f"(d[2]), "+f"(d[3])
        : "r"(a0), "r"(a1), "r"(a2), "r"(a3), "r"(b0), "r"(b1));
}

#define LDSM_X4(r0, r1, r2, r3, addr) \
    asm volatile("ldmatrix.sync.aligned.m8n8.x4.shared.b16 {%0,%1,%2,%3}, [%4];" \
        : "=r"(r0), "=r"(r1), "=r"(r2), "=r"(r3) : "r"(addr))

#define CP_ASYNC16(s, g) \
    asm volatile("cp.async.cg.shared.global [%0], [%1], 16;" :: "r"(s), "l"(g))
#define CP_COMMIT() asm volatile("cp.async.commit_group;" ::: "memory")
#define CP_WAITG(n) asm volatile("cp.async.wait_group %0;" :: "n"(n) : "memory")

// ---------------- kernel: bias gather ----------------
__global__ void bias_kernel(const float* __restrict__ table, const int* __restrict__ rel) {
    int idx = blockIdx.x * 256 + threadIdx.x;
    if (idx < NH * NTOK * NTOK) {
        int h = idx / (NTOK * NTOK);
        int nm = idx - h * (NTOK * NTOK);
        g_bias[idx] = table[rel[nm] * NH + h];
    }
}

// ---------------- kernels: fp32 -> fp16 hi/lo ----------------
__global__ void conv_x(const float* __restrict__ x) {
    size_t i = (size_t)blockIdx.x * 256 + threadIdx.x;
    if (i < (size_t)MTOT * DIM / 4) {
        float4 v = ((const float4*)x)[i];
        unsigned short h0, h1, h2, h3, l0, l1, l2, l3;
        split_h(v.x, h0, l0); split_h(v.y, h1, l1);
        split_h(v.z, h2, l2); split_h(v.w, h3, l3);
        ((uint2*)g_xhi)[i] = make_uint2((u32)h0 | ((u32)h1 << 16), (u32)h2 | ((u32)h3 << 16));
        ((uint2*)g_xlo)[i] = make_uint2((u32)l0 | ((u32)l1 << 16), (u32)l2 | ((u32)l3 << 16));
    }
}
// hi-only conversion of both weight matrices in one launch
__global__ void conv_w(const float* __restrict__ wq, const float* __restrict__ wp) {
    int i = blockIdx.x * 256 + threadIdx.x;
    const int nq4 = 768 * 256 / 4;
    const int np4 = 256 * 256 / 4;
    if (i < nq4) {
        float4 v = ((const float4*)wq)[i];
        ((uint2*)g_wqhi)[i] = make_uint2(
            (u32)__half_as_ushort(__float2half_rn(v.x)) | ((u32)__half_as_ushort(__float2half_rn(v.y)) << 16),
            (u32)__half_as_ushort(__float2half_rn(v.z)) | ((u32)__half_as_ushort(__float2half_rn(v.w)) << 16));
    } else if (i < nq4 + np4) {
        int j = i - nq4;
        float4 v = ((const float4*)wp)[j];
        ((uint2*)g_wphi)[j] = make_uint2(
            (u32)__half_as_ushort(__float2half_rn(v.x)) | ((u32)__half_as_ushort(__float2half_rn(v.y)) << 16),
            (u32)__half_as_ushort(__float2half_rn(v.z)) | ((u32)__half_as_ushort(__float2half_rn(v.w)) << 16));
    }
}

// -------- tensor-core GEMM (fp16 2-term: Ah*Bh + Al*Bh; K32 3-stage ring) --------
#define KC      32
#define RSTRIDE 40                          /* elements; 80B rows, conflict-free */
#define TILE_E  (128 * RSTRIDE)
#define TILE_B  (TILE_E * 2)                /* 10240 B */
#define STAGE_B (3 * TILE_B)                /* Ah, Al, Bh = 30720 B */
#define NSTAGE  3
#define SMEM_BYTES (NSTAGE * STAGE_B)       /* 92160 -> still 2 CTAs/SM */

template <int MODE>
__global__ __launch_bounds__(256)
void gemm_mma(const float* __restrict__ bias, float* __restrict__ out) {
    extern __shared__ __half sm[];

    const __half* Ah = MODE ? g_ahi : g_xhi;
    const __half* Al = MODE ? g_alo : g_xlo;
    const __half* Bh = MODE ? g_wphi : g_wqhi;

    const int tid  = threadIdx.x;
    const int warp = tid >> 5;
    const int lane = tid & 31;
    const int g    = lane >> 2;
    const int t4   = lane & 3;
    const int wm   = warp >> 2;       // 0..1
    const int wn   = warp & 3;        // 0..3

    // N-block fastest -> concurrent CTAs share A slice in L2
    const int    o0 = blockIdx.x * 128;
    const size_t m0 = (size_t)blockIdx.y * 128;

    const u32 smem_base = smem_u32(sm);

    // gmem -> smem copy mapping: 2 x 16B per tile per thread
    const int row0 = tid >> 2;
    const int row1 = row0 + 64;
    const int seg  = (tid & 3) * 8;

    const __half* gA0h = Ah + (m0 + row0) * 256 + seg;
    const __half* gA1h = Ah + (m0 + row1) * 256 + seg;
    const __half* gA0l = Al + (m0 + row0) * 256 + seg;
    const __half* gA1l = Al + (m0 + row1) * 256 + seg;
    const __half* gB0h = Bh + (size_t)(o0 + row0) * 256 + seg;
    const __half* gB1h = Bh + (size_t)(o0 + row1) * 256 + seg;

    const u32 s0b = (u32)(row0 * RSTRIDE + seg) * 2;
    const u32 s1b = (u32)(row1 * RSTRIDE + seg) * 2;

    // ldmatrix per-lane offsets (bytes, relative to stage base)
    const int q3 = (lane >> 3) & 1;
    const int q4 = (lane >> 4) & 1;
    const int r8 = lane & 7;
    const u32 offA  = 0 * TILE_B + (u32)(((wm * 64 + q3 * 8 + r8) * RSTRIDE) + q4 * 8) * 2;
    const u32 offB0 = 2 * TILE_B + (u32)(((wn * 32 + 0 * 16 + q4 * 8 + r8) * RSTRIDE) + q3 * 8) * 2;
    const u32 offB1 = 2 * TILE_B + (u32)(((wn * 32 + 1 * 16 + q4 * 8 + r8) * RSTRIDE) + q3 * 8) * 2;

    float acc[4][4][4];
#pragma unroll
    for (int a = 0; a < 4; ++a)
#pragma unroll
        for (int b = 0; b < 4; ++b)
#pragma unroll
            for (int c = 0; c < 4; ++c) acc[a][b][c] = 0.f;

#define ISSUE_STAGE(stg, kb) do {                                      \
        const u32 nx = smem_base + (u32)(stg) * STAGE_B;               \
        CP_ASYNC16(nx + 0 * TILE_B + s0b, gA0h + (kb));                \
        CP_ASYNC16(nx + 0 * TILE_B + s1b, gA1h + (kb));                \
        CP_ASYNC16(nx + 1 * TILE_B + s0b, gA0l + (kb));                \
        CP_ASYNC16(nx + 1 * TILE_B + s1b, gA1l + (kb));                \
        CP_ASYNC16(nx + 2 * TILE_B + s0b, gB0h + (kb));                \
        CP_ASYNC16(nx + 2 * TILE_B + s1b, gB1h + (kb));                \
        CP_COMMIT();                                                   \
    } while (0)

    // ---- prologue: 2 stages in flight ----
    ISSUE_STAGE(0, 0);
    ISSUE_STAGE(1, KC);

    int cur = 0;   // ring index of chunk kc
#pragma unroll 1
    for (int kc = 0; kc < 8; ++kc) {
        if (kc < 7) CP_WAITG(1);
        else        CP_WAITG(0);
        __syncthreads();

        // refill the stage freed at kc-1 (ring slot (kc+2)%3)
        if (kc + 2 < 8) {
            int nxt = cur + 2; if (nxt >= 3) nxt -= 3;
            ISSUE_STAGE(nxt, (kc + 2) * KC);
        }

        const u32 stb = smem_base + (u32)cur * STAGE_B;
#pragma unroll
        for (int ks = 0; ks < 2; ++ks) {
            const u32 kso = (u32)(ks * 32);
            u32 bh[4][2];
            LDSM_X4(bh[0][0], bh[0][1], bh[1][0], bh[1][1], stb + offB0 + kso);
            LDSM_X4(bh[2][0], bh[2][1], bh[3][0], bh[3][1], stb + offB1 + kso);
#pragma unroll
            for (int mi = 0; mi < 4; ++mi) {
                const u32 ao = stb + offA + (u32)(mi * 16 * RSTRIDE * 2) + kso;
                u32 ah0, ah1, ah2, ah3, al0, al1, al2, al3;
                LDSM_X4(ah0, ah1, ah2, ah3, ao);
                LDSM_X4(al0, al1, al2, al3, ao + TILE_B);
#pragma unroll
                for (int ni = 0; ni < 4; ++ni) {
                    mma16816(acc[mi][ni], ah0, ah1, ah2, ah3, bh[ni][0], bh[ni][1]);
                    mma16816(acc[mi][ni], al0, al1, al2, al3, bh[ni][0], bh[ni][1]);
                }
            }
        }
        if (++cur == 3) cur = 0;
    }
#undef ISSUE_STAGE

    // ---- epilogue: bias add + store straight from registers ----
#pragma unroll
    for (int mi = 0; mi < 4; ++mi) {
        const int r0 = (int)m0 + wm * 64 + mi * 16 + g;
        const int r1 = r0 + 8;
#pragma unroll
        for (int ni = 0; ni < 4; ++ni) {
            const int c = o0 + wn * 32 + ni * 8 + 2 * t4;
            const float b0 = bias[c], b1 = bias[c + 1];
            float v00 = acc[mi][ni][0] + b0, v01 = acc[mi][ni][1] + b1;
            float v10 = acc[mi][ni][2] + b0, v11 = acc[mi][ni][3] + b1;
            if (MODE == 0) {
                const int which = c >> 8;
                const int head  = (c >> 5) & 7;
                const int d     = c & 31;
#pragma unroll
                for (int rr = 0; rr < 2; ++rr) {
                    const int m = rr ? r1 : r0;
                    const int bwin = m / NTOK;
                    const int n = m - bwin * NTOK;
                    float* dst = g_qkv + (size_t)which * QKV_S +
                        (((size_t)bwin * NH + head) * NTOK + n) * HD + d;
                    *(float2*)dst = rr ? make_float2(v10, v11) : make_float2(v00, v01);
                }
            } else {
                *(float2*)(out + (size_t)r0 * 256 + c) = make_float2(v00, v01);
                *(float2*)(out + (size_t)r1 * 256 + c) = make_float2(v10, v11);
            }
        }
    }
}

// ---------------- fused window attention (f32x2 register tiles) ----------------
__global__ __launch_bounds__(64)
void attn_kernel() {
    __shared__ __align__(16) float sq[NTOK][34], sk[NTOK][34], sv[NTOK][34];
    __shared__ float s[NTOK][50];

    const int tid = threadIdx.x;
    const int bh = blockIdx.x;
    const int bwin = bh >> 3;
    const int h = bh & 7;

    const size_t base = (size_t)bh * (NTOK * HD);
    const float4* q4 = (const float4*)(g_qkv + base);
    const float4* k4 = (const float4*)(g_qkv + (size_t)QKV_S + base);
    const float4* v4 = (const float4*)(g_qkv + 2ULL * QKV_S + base);

    for (int i = tid; i < NTOK * HD / 4; i += 64) {
        const int r = i >> 3, c = (i & 7) * 4;
        float4 a = q4[i];
        sq[r][c] = a.x; sq[r][c + 1] = a.y; sq[r][c + 2] = a.z; sq[r][c + 3] = a.w;
        float4 b = k4[i];
        sk[r][c] = b.x; sk[r][c + 1] = b.y; sk[r][c + 2] = b.z; sk[r][c + 3] = b.w;
        float4 d = v4[i];
        sv[r][c] = d.x; sv[r][c + 1] = d.y; sv[r][c + 2] = d.z; sv[r][c + 3] = d.w;
    }
    __syncthreads();

    if (tid < 49) {
        const int ti = tid / 7, tj = tid - ti * 7;
        const int n0 = ti * 7, m0 = tj * 7;
        u64 acc[7][7];
#pragma unroll
        for (int r = 0; r < 7; ++r)
#pragma unroll
            for (int cc = 0; cc < 7; ++cc) acc[r][cc] = 0ull;
#pragma unroll
        for (int kk = 0; kk < 16; ++kk) {
            u64 qv[7], kv[7];
#pragma unroll
            for (int r = 0; r < 7; ++r) qv[r] = *(const u64*)&sq[n0 + r][2 * kk];
#pragma unroll
            for (int cc = 0; cc < 7; ++cc) kv[cc] = *(const u64*)&sk[m0 + cc][2 * kk];
#pragma unroll
            for (int r = 0; r < 7; ++r)
#pragma unroll
                for (int cc = 0; cc < 7; ++cc) acc[r][cc] = f2fma(qv[r], kv[cc], acc[r][cc]);
        }
        const float scale = 0.17677669529663687f;
        const float* bb = g_bias + h * (NTOK * NTOK);
#pragma unroll
        for (int r = 0; r < 7; ++r)
#pragma unroll
            for (int cc = 0; cc < 7; ++cc) {
                const u64 a = acc[r][cc];
                const float lo = __uint_as_float((u32)(a & 0xffffffffull));
                const float hi = __uint_as_float((u32)(a >> 32));
                s[n0 + r][m0 + cc] = (lo + hi) * scale + bb[(n0 + r) * NTOK + m0 + cc];
            }
    }
    __syncthreads();

    if (tid < 49) {
        float mx = -1e30f;
#pragma unroll
        for (int c = 0; c < NTOK; ++c) mx = fmaxf(mx, s[tid][c]);
        float sum = 0.f;
#pragma unroll
        for (int c = 0; c < NTOK; ++c) {
            float e = __expf(s[tid][c] - mx);
            s[tid][c] = e;
            sum += e;
        }
        const float inv = 1.f / sum;
#pragma unroll
        for (int c = 0; c < NTOK; ++c) s[tid][c] *= inv;
    }
    __syncthreads();

    // P @ V: 56 threads (2 warps), 7(n) x 4(d) register tiles, f32x2 along d
    if (tid < 56) {
        const int ti = tid >> 3, tj = tid & 7;     // 7 n-groups x 8 d-groups
        const int n0 = ti * 7, d0 = tj * 4;
        u64 acc2[7][2];
#pragma unroll
        for (int r = 0; r < 7; ++r) { acc2[r][0] = 0ull; acc2[r][1] = 0ull; }
#pragma unroll 7
        for (int m = 0; m < NTOK; ++m) {
            const u64 v0 = *(const u64*)&sv[m][d0];
            const u64 v1 = *(const u64*)&sv[m][d0 + 2];
#pragma unroll
            for (int r = 0; r < 7; ++r) {
                const u64 sd = dup32(s[n0 + r][m]);
                acc2[r][0] = f2fma(sd, v0, acc2[r][0]);
                acc2[r][1] = f2fma(sd, v1, acc2[r][1]);
            }
        }
#pragma unroll
        for (int r = 0; r < 7; ++r) {
            unsigned short hh[4], ll[4];
#pragma unroll
            for (int cc = 0; cc < 2; ++cc) {
                const u64 a = acc2[r][cc];
                split_h(__uint_as_float((u32)(a & 0xffffffffull)), hh[2 * cc], ll[2 * cc]);
                split_h(__uint_as_float((u32)(a >> 32)), hh[2 * cc + 1], ll[2 * cc + 1]);
            }
            uint2 vh = make_uint2((u32)hh[0] | ((u32)hh[1] << 16), (u32)hh[2] | ((u32)hh[3] << 16));
            uint2 vl = make_uint2((u32)ll[0] | ((u32)ll[1] << 16), (u32)ll[2] | ((u32)ll[3] << 16));
            const size_t off = ((size_t)bwin * NTOK + n0 + r) * 256 + h * 32 + d0;
            *(uint2*)(g_ahi + off) = vh;
            *(uint2*)(g_alo + off) = vl;
        }
    }
}

// ---------------- launch ----------------
extern "C" void kernel_launch(void* const* d_in, const int* in_sizes, int n_in,
                              void* d_out, int out_size) {
    const float* x      = (const float*)d_in[0];
    const float* qkv_w  = (const float*)d_in[1];
    const float* qkv_b  = (const float*)d_in[2];
    const float* proj_w = (const float*)d_in[3];
    const float* proj_b = (const float*)d_in[4];
    const float* table  = (const float*)d_in[5];
    const int*   rel    = (const int*)d_in[6];
    float* out = (float*)d_out;

    static int smem_set = 0;
    if (!smem_set) {
        cudaFuncSetAttribute(gemm_mma<0>, cudaFuncAttributeMaxDynamicSharedMemorySize, SMEM_BYTES);
        cudaFuncSetAttribute(gemm_mma<1>, cudaFuncAttributeMaxDynamicSharedMemorySize, SMEM_BYTES);
        smem_set = 1;
    }

    bias_kernel<<<(NH * NTOK * NTOK + 255) / 256, 256>>>(table, rel);
    conv_x<<<(int)(((size_t)MTOT * DIM / 4 + 255) / 256), 256>>>(x);
    conv_w<<<((768 + 256) * 256 / 4 + 255) / 256, 256>>>(qkv_w, proj_w);
    gemm_mma<0><<<dim3(6, MTOT / 128), 256, SMEM_BYTES>>>(qkv_b, nullptr);
    attn_kernel<<<BWIN * NH, 64>>>();
    gemm_mma<1><<<dim3(2, MTOT / 128), 256, SMEM_BYTES>>>(proj_b, out);
}